// round 2
// baseline (speedup 1.0000x reference)
#include <cuda_runtime.h>
#include <cstdint>

// ---------------- problem constants ----------------
#define Bq   16
#define Mq   2048
#define Kq   40
#define Nq   (Bq*Mq)      // 32768
#define INC  96
#define SDQ  4
#define PDQ  22
#define H1   128
#define CAND 192

static const size_t ZOFF = (size_t)Nq * 96;        // floats before edge_index
static const size_t NKq  = (size_t)Nq * Kq;

// ---------------- device scratch (no cudaMalloc allowed) ----------------
__device__ float g_s[Nq * SDQ];
__device__ float g_h[Nq * PDQ];
__device__ float g_aggr[Nq * 2 * PDQ];
__device__ float g_out[Nq * 96];
__device__ float g_t[Nq * H1];
__device__ float g_y[Nq * 96];
__device__ float g_c3[Bq * 96];

// ================= K0: s = x@W_s + b_s ; h = x@W_h + b_h =================
// block: 256 threads, 8 nodes/block; lane = output dim (0..3 -> s, 4..25 -> h)
__global__ __launch_bounds__(256) void sh_kernel(
    const float* __restrict__ x,
    const float* __restrict__ Ws, const float* __restrict__ bs,
    const float* __restrict__ Wh, const float* __restrict__ bh)
{
    __shared__ float wsh[INC * 26];
    __shared__ float xs[8][INC];
    int tid = threadIdx.x;
    for (int idx = tid; idx < INC * 26; idx += 256) {
        int k = idx / 26, od = idx % 26;
        wsh[idx] = (od < SDQ) ? Ws[k * SDQ + od] : Wh[k * PDQ + (od - SDQ)];
    }
    const float* xb = x + (size_t)blockIdx.x * 8 * INC;
    for (int idx = tid; idx < 8 * INC; idx += 256) xs[idx / INC][idx % INC] = xb[idx];
    __syncthreads();

    int nl = tid >> 5, od = tid & 31;
    if (od < 26) {
        float acc = 0.f;
        #pragma unroll 8
        for (int k = 0; k < INC; k++) acc = fmaf(xs[nl][k], wsh[k * 26 + od], acc);
        int n = blockIdx.x * 8 + nl;
        if (od < SDQ) g_s[n * SDQ + od] = acc + bs[od];
        else          g_h[n * PDQ + (od - SDQ)] = acc + bh[od - SDQ];
    }
}

// ================= K1: kNN + weighted mean/max aggregation + edges =======
// 1 warp per query node, 8 warps/block. s-tile of the event in shared (32KB).
// Exact top-K (ascending d2, tie-break lower index) via bit-pattern binary
// search -> candidate compaction (<=192) -> 40x argmin-with-removal.
__global__ __launch_bounds__(256, 2) void knn_kernel(float* __restrict__ dout)
{
    __shared__ float ss[Mq * SDQ];                       // 32768 B
    __shared__ unsigned long long cand[8][CAND];         // 12288 B

    int tid  = threadIdx.x;
    int lane = tid & 31;
    int w    = tid >> 5;
    int ev    = blockIdx.x >> 8;                 // 256 blocks / event
    int qloc0 = (blockIdx.x & 255) * 8;

    const float* sev = g_s + (size_t)ev * Mq * SDQ;
    for (int i4 = tid; i4 < Mq * SDQ / 4; i4 += 256)
        ((float4*)ss)[i4] = ((const float4*)sev)[i4];
    __syncthreads();

    int qloc = qloc0 + w;
    int i = ev * Mq + qloc;
    float4 sq = ((float4*)ss)[qloc];

    // ---- distances (d2 >= 0 so float bits are order-preserving as u32) ----
    unsigned bits[64];
    #pragma unroll
    for (int t = 0; t < 64; t++) {
        int j = lane + 32 * t;
        float4 sj = ((float4*)ss)[j];
        float dx = sq.x - sj.x, dy = sq.y - sj.y, dz = sq.z - sj.z, dw = sq.w - sj.w;
        float d2 = fmaf(dx, dx, fmaf(dy, dy, fmaf(dz, dz, dw * dw)));
        bits[t] = __float_as_uint(d2);
    }

    // ---- binary search for threshold with K <= count <= CAND ----
    unsigned lo = 0u, hi = 0x7f800000u, T = 0u;
    bool found = false;
    for (int it = 0; it < 32 && !found; ++it) {
        unsigned mid = lo + ((hi - lo) >> 1);
        int c = 0;
        #pragma unroll
        for (int t = 0; t < 64; t++) c += (bits[t] <= mid) ? 1 : 0;
        c = __reduce_add_sync(0xffffffffu, c);
        if (c >= Kq && c <= CAND) { T = mid; found = true; }
        else if (c >= Kq) hi = mid;
        else lo = mid;
        if (!found && hi - lo <= 1u) { T = hi; found = true; }
    }
    if (!found) T = hi;

    // ---- compact candidates (order within buffer irrelevant) ----
    int base = 0;
    #pragma unroll
    for (int t = 0; t < 64; t++) {
        bool p = (bits[t] <= T);
        unsigned m = __ballot_sync(0xffffffffu, p);
        if (p) {
            int pos = base + __popc(m & ((1u << lane) - 1u));
            if (pos < CAND)
                cand[w][pos] = ((unsigned long long)bits[t] << 32) | (unsigned)(lane + 32 * t);
        }
        base += __popc(m);
    }
    int C = base < CAND ? base : CAND;
    __syncwarp();

    // ---- K x (argmin + remove) ; fused exp-weight aggregation ----
    float meanAcc = 0.f;
    float maxAcc  = __int_as_float(0xff800000);   // -inf
    const float* hev = g_h + (size_t)ev * Mq * PDQ;
    float* esrc = dout + ZOFF + (size_t)i * Kq;
    float* etgt = esrc + NKq;

    for (int r = 0; r < Kq; r++) {
        unsigned long long best = ~0ull; int slot = -1;
        #pragma unroll
        for (int u = 0; u < CAND / 32; u++) {
            int ci = lane + 32 * u;
            if (ci < C) {
                unsigned long long v = cand[w][ci];
                if (v < best) { best = v; slot = ci; }
            }
        }
        unsigned long long mval = best;
        #pragma unroll
        for (int o = 16; o; o >>= 1) {
            unsigned long long other = __shfl_xor_sync(0xffffffffu, mval, o);
            if (other < mval) mval = other;
        }
        if (best == mval && slot >= 0) cand[w][slot] = ~0ull;   // unique key
        __syncwarp();

        float d2  = __uint_as_float((unsigned)(mval >> 32));
        int   j   = (int)(mval & 0xffffffffu);
        float wgt = __expf(-10.f * d2);
        if (lane < PDQ) {
            float msg = hev[(size_t)j * PDQ + lane] * wgt;
            meanAcc += msg;
            maxAcc = fmaxf(maxAcc, msg);
        } else if (lane == 24) {
            esrc[r] = (float)(ev * Mq + j);
        } else if (lane == 25) {
            etgt[r] = (float)i;
        }
    }
    if (lane < PDQ) {
        float* ag = g_aggr + (size_t)i * 2 * PDQ;
        ag[lane]       = meanAcc * (1.f / (float)Kq);
        ag[PDQ + lane] = maxAcc;
    }
}

// ================= generic row-tiled SIMT GEMM ===========================
// block: 128 thr, 64 rows; thread tile 8 rows x CPT cols (interleaved cols).
template<int KD, int OC, int CPT, bool DOTANH, bool EVBIAS>
__global__ __launch_bounds__(128) void gemm_k(
    const float* __restrict__ A, const float* __restrict__ W,
    const float* __restrict__ bias, float* __restrict__ Cf)
{
    constexpr int RT = 64, AST = KD + 1;
    extern __shared__ float sm[];
    float* As = sm;                 // RT*AST
    float* Wsm = sm + RT * AST;     // KD*OC
    int rowBase = blockIdx.x * RT;

    for (int idx = threadIdx.x; idx < RT * KD; idx += 128) {
        int r = idx / KD, k = idx - r * KD;
        As[r * AST + k] = A[(size_t)rowBase * KD + idx];
    }
    for (int idx = threadIdx.x; idx < KD * OC; idx += 128) Wsm[idx] = W[idx];
    __syncthreads();

    int cg = threadIdx.x & 15, rg = threadIdx.x >> 4;
    int r0 = rg * 8;
    float acc[8][CPT];
    if (EVBIAS) {
        int evb = rowBase >> 11;
        #pragma unroll
        for (int c = 0; c < CPT; c++) {
            float bv = bias[evb * 96 + cg + 16 * c];
            #pragma unroll
            for (int r = 0; r < 8; r++) acc[r][c] = bv;
        }
    } else {
        #pragma unroll
        for (int c = 0; c < CPT; c++) {
            float bv = bias[cg + 16 * c];
            #pragma unroll
            for (int r = 0; r < 8; r++) acc[r][c] = bv;
        }
    }

    const float* aP = As + r0 * AST;
    #pragma unroll 4
    for (int k = 0; k < KD; k++) {
        float a[8];
        #pragma unroll
        for (int r = 0; r < 8; r++) a[r] = aP[r * AST + k];
        #pragma unroll
        for (int c = 0; c < CPT; c++) {
            float wv = Wsm[k * OC + cg + 16 * c];
            #pragma unroll
            for (int r = 0; r < 8; r++) acc[r][c] = fmaf(a[r], wv, acc[r][c]);
        }
    }

    #pragma unroll
    for (int r = 0; r < 8; r++) {
        size_t rowoff = (size_t)(rowBase + r0 + r) * OC;
        #pragma unroll
        for (int c = 0; c < CPT; c++) {
            float v = acc[r][c];
            if (DOTANH) v = tanhf(v);
            Cf[rowoff + cg + 16 * c] = v;
        }
    }
}

// ================= K2a: out = x@W_o1 + aggr@W_o2 + b_o2 ==================
__global__ __launch_bounds__(128) void gemm_out_k(
    const float* __restrict__ x, const float* __restrict__ aggr,
    const float* __restrict__ Wo1, const float* __restrict__ Wo2,
    const float* __restrict__ bias, float* __restrict__ outp)
{
    constexpr int RT = 64, KD1 = 96, KD2 = 44, OC = 96, CPT = 6;
    extern __shared__ float sm[];
    float* As1 = sm;                        // 64*97
    float* As2 = As1 + RT * (KD1 + 1);      // 64*45
    float* Ws1 = As2 + RT * (KD2 + 1);      // 96*96
    float* Ws2 = Ws1 + KD1 * OC;            // 44*96
    int rowBase = blockIdx.x * RT;

    for (int idx = threadIdx.x; idx < RT * KD1; idx += 128) {
        int r = idx / KD1, k = idx - r * KD1;
        As1[r * (KD1 + 1) + k] = x[(size_t)rowBase * KD1 + idx];
    }
    for (int idx = threadIdx.x; idx < RT * KD2; idx += 128) {
        int r = idx / KD2, k = idx - r * KD2;
        As2[r * (KD2 + 1) + k] = aggr[(size_t)rowBase * KD2 + idx];
    }
    for (int idx = threadIdx.x; idx < KD1 * OC; idx += 128) Ws1[idx] = Wo1[idx];
    for (int idx = threadIdx.x; idx < KD2 * OC; idx += 128) Ws2[idx] = Wo2[idx];
    __syncthreads();

    int cg = threadIdx.x & 15, rg = threadIdx.x >> 4;
    int r0 = rg * 8;
    float acc[8][CPT];
    #pragma unroll
    for (int c = 0; c < CPT; c++) {
        float bv = bias[cg + 16 * c];
        #pragma unroll
        for (int r = 0; r < 8; r++) acc[r][c] = bv;
    }

    const float* aP1 = As1 + r0 * (KD1 + 1);
    #pragma unroll 4
    for (int k = 0; k < KD1; k++) {
        float a[8];
        #pragma unroll
        for (int r = 0; r < 8; r++) a[r] = aP1[r * (KD1 + 1) + k];
        #pragma unroll
        for (int c = 0; c < CPT; c++) {
            float wv = Ws1[k * OC + cg + 16 * c];
            #pragma unroll
            for (int r = 0; r < 8; r++) acc[r][c] = fmaf(a[r], wv, acc[r][c]);
        }
    }
    const float* aP2 = As2 + r0 * (KD2 + 1);
    #pragma unroll 4
    for (int k = 0; k < KD2; k++) {
        float a[8];
        #pragma unroll
        for (int r = 0; r < 8; r++) a[r] = aP2[r * (KD2 + 1) + k];
        #pragma unroll
        for (int c = 0; c < CPT; c++) {
            float wv = Ws2[k * OC + cg + 16 * c];
            #pragma unroll
            for (int r = 0; r < 8; r++) acc[r][c] = fmaf(a[r], wv, acc[r][c]);
        }
    }

    #pragma unroll
    for (int r = 0; r < 8; r++) {
        size_t rowoff = (size_t)(rowBase + r0 + r) * OC;
        #pragma unroll
        for (int c = 0; c < CPT; c++) outp[rowoff + cg + 16 * c] = acc[r][c];
    }
}

// ================= K3: per-event mean/min/max + stats@W3[0:288]+b3 =======
__global__ __launch_bounds__(192) void stats_k(
    const float* __restrict__ W3, const float* __restrict__ b3)
{
    int ev = blockIdx.x, tid = threadIdx.x;
    __shared__ float red[3][192];
    __shared__ float st[288];

    float sm = 0.f, mn = __int_as_float(0x7f800000), mx = __int_as_float(0xff800000);
    {
        int d = tid % 96, half = tid / 96;     // tid < 192 always (block=192)
        const float* yb = g_y + (size_t)ev * Mq * 96;
        for (int r = half; r < Mq; r += 2) {
            float v = yb[(size_t)r * 96 + d];
            sm += v; mn = fminf(mn, v); mx = fmaxf(mx, v);
        }
        red[0][tid] = sm; red[1][tid] = mn; red[2][tid] = mx;
    }
    __syncthreads();
    if (tid < 96) {
        st[tid]       = (red[0][tid] + red[0][tid + 96]) * (1.f / (float)Mq);
        st[96 + tid]  = fminf(red[1][tid], red[1][tid + 96]);
        st[192 + tid] = fmaxf(red[2][tid], red[2][tid + 96]);
    }
    __syncthreads();
    if (tid < 96) {
        float acc = b3[tid];
        #pragma unroll 4
        for (int k = 0; k < 288; k++) acc = fmaf(st[k], W3[(size_t)k * 96 + tid], acc);
        g_c3[ev * 96 + tid] = acc;
    }
}

// ================= host launcher =========================================
extern "C" void kernel_launch(void* const* d_in, const int* in_sizes, int n_in,
                              void* d_out, int out_size)
{
    (void)out_size;
    // dict-order expected element counts:
    // x, batch, W_s, b_s, W_h, b_h, W_o1, W_o2, b_o2, W1, b1, W2, b2, W3, b3
    static const int EXPECTED[15] = {
        3145728, 32768, 384, 4, 2112, 22, 9216, 4224, 96, 12288, 128, 12288, 96, 36864, 96
    };
    const void* P[15];
    bool ok = (n_in >= 15);
    if (ok) for (int i = 0; i < 15; i++) if (in_sizes[i] != EXPECTED[i]) { ok = false; break; }
    if (ok) {
        for (int i = 0; i < 15; i++) P[i] = d_in[i];
    } else {
        bool used[64] = {false};
        for (int r = 0; r < 15; r++) {
            P[r] = nullptr;
            for (int j = 0; j < n_in && j < 64; j++) {
                if (!used[j] && in_sizes[j] == EXPECTED[r]) { P[r] = d_in[j]; used[j] = true; break; }
            }
        }
    }

    const float* x   = (const float*)P[0];
    const float* Ws  = (const float*)P[2];
    const float* bs  = (const float*)P[3];
    const float* Wh  = (const float*)P[4];
    const float* bh  = (const float*)P[5];
    const float* Wo1 = (const float*)P[6];
    const float* Wo2 = (const float*)P[7];
    const float* bo2 = (const float*)P[8];
    const float* W1  = (const float*)P[9];
    const float* b1  = (const float*)P[10];
    const float* W2  = (const float*)P[11];
    const float* b2  = (const float*)P[12];
    const float* W3  = (const float*)P[13];
    const float* b3  = (const float*)P[14];
    float* dout = (float*)d_out;

    float *p_aggr, *p_out, *p_t, *p_y, *p_c3;
    cudaGetSymbolAddress((void**)&p_aggr, g_aggr);
    cudaGetSymbolAddress((void**)&p_out,  g_out);
    cudaGetSymbolAddress((void**)&p_t,    g_t);
    cudaGetSymbolAddress((void**)&p_y,    g_y);
    cudaGetSymbolAddress((void**)&p_c3,   g_c3);

    const int SMEM_OUT = (64 * 97 + 64 * 45 + 96 * 96 + 44 * 96) * 4;  // 90112
    const int SMEM_B   = (64 * 97 + 96 * 128) * 4;                      // 73984
    const int SMEM_C   = (64 * 129 + 128 * 96) * 4;                     // 82176
    const int SMEM_Z   = (64 * 97 + 96 * 96) * 4;                       // 61696
    cudaFuncSetAttribute(gemm_out_k, cudaFuncAttributeMaxDynamicSharedMemorySize, SMEM_OUT);
    cudaFuncSetAttribute(gemm_k<96, 128, 8, true,  false>,
                         cudaFuncAttributeMaxDynamicSharedMemorySize, SMEM_B);
    cudaFuncSetAttribute(gemm_k<128, 96, 6, true,  false>,
                         cudaFuncAttributeMaxDynamicSharedMemorySize, SMEM_C);
    cudaFuncSetAttribute(gemm_k<96,  96, 6, true,  true>,
                         cudaFuncAttributeMaxDynamicSharedMemorySize, SMEM_Z);

    // K0: spatial coords + propagated features
    sh_kernel<<<Nq / 8, 256>>>(x, Ws, bs, Wh, bh);
    // K1: kNN + aggregation + edge_index (writes src/tgt floats into d_out)
    knn_kernel<<<Nq / 8, 256>>>(dout);
    // K2a: out = x@W_o1 + aggr@W_o2 + b_o2
    gemm_out_k<<<Nq / 64, 128, SMEM_OUT>>>(x, p_aggr, Wo1, Wo2, bo2, p_out);
    // K2b: t = tanh(out@W1 + b1)
    gemm_k<96, 128, 8, true, false><<<Nq / 64, 128, SMEM_B>>>(p_out, W1, b1, p_t);
    // K2c: y = tanh(t@W2 + b2)
    gemm_k<128, 96, 6, true, false><<<Nq / 64, 128, SMEM_C>>>(p_t, W2, b2, p_y);
    // K3: per-event stats + stats@W3[0:288] + b3
    stats_k<<<Bq, 192>>>(W3, b3);
    // K4: z = tanh(c3[event] + y@W3[288:384]) -> floats at d_out[0:N*96]
    gemm_k<96, 96, 6, true, true><<<Nq / 64, 128, SMEM_Z>>>(p_y, W3 + 288 * 96, p_c3, dout);
}

// round 3
// speedup vs baseline: 1.1604x; 1.1604x over previous
#include <cuda_runtime.h>
#include <cstdint>

// ---------------- problem constants ----------------
#define Bq   16
#define Mq   2048
#define Kq   40
#define Nq   (Bq*Mq)      // 32768
#define INC  96
#define SDQ  4
#define PDQ  22
#define H1   128
#define CAND 128

static const size_t ZOFF = (size_t)Nq * 96;        // floats before edge_index
static const size_t NKq  = (size_t)Nq * Kq;

// ---------------- device scratch ----------------
__device__ float g_s[Nq * SDQ];
__device__ float g_h[Nq * PDQ];
__device__ float g_aggr[Nq * 2 * PDQ];
__device__ float g_out[Nq * 96];
__device__ float g_t[Nq * H1];
__device__ float g_y[Nq * 96];
__device__ float g_c3[Bq * 96];
__device__ float g_part[Bq * 16 * 3 * 96];

__device__ __forceinline__ float fast_tanh(float v) {
    float e = __expf(2.f * v);
    return (e - 1.f) * __frcp_rn(e + 1.f);
}

// ================= K0: s = x@W_s + b_s ; h = x@W_h + b_h =================
__global__ __launch_bounds__(256) void sh_kernel(
    const float* __restrict__ x,
    const float* __restrict__ Ws, const float* __restrict__ bs,
    const float* __restrict__ Wh, const float* __restrict__ bh)
{
    __shared__ float wsh[INC * 26];
    __shared__ float xs[8][INC];
    int tid = threadIdx.x;
    for (int idx = tid; idx < INC * 26; idx += 256) {
        int k = idx / 26, od = idx % 26;
        wsh[idx] = (od < SDQ) ? Ws[k * SDQ + od] : Wh[k * PDQ + (od - SDQ)];
    }
    const float* xb = x + (size_t)blockIdx.x * 8 * INC;
    for (int idx = tid; idx < 8 * INC; idx += 256) xs[idx / INC][idx % INC] = xb[idx];
    __syncthreads();

    int nl = tid >> 5, od = tid & 31;
    if (od < 26) {
        float acc = 0.f;
        #pragma unroll 8
        for (int k = 0; k < INC; k++) acc = fmaf(xs[nl][k], wsh[k * 26 + od], acc);
        int n = blockIdx.x * 8 + nl;
        if (od < SDQ) g_s[n * SDQ + od] = acc + bs[od];
        else          g_h[n * PDQ + (od - SDQ)] = acc + bh[od - SDQ];
    }
}

// ================= K1: kNN + weighted mean/max aggregation + edges =======
// 1 warp per query; model-guided threshold search -> <=128 candidates ->
// register bitonic sort (exact (d2bits,idx) ascending) -> top-40 broadcast.
__global__ __launch_bounds__(256, 2) void knn_kernel(float* __restrict__ dout)
{
    __shared__ float ss[Mq * SDQ];                       // 32768 B
    __shared__ unsigned long long cand[8][CAND];         // 8192 B

    int tid  = threadIdx.x;
    int lane = tid & 31;
    int w    = tid >> 5;
    int ev    = blockIdx.x >> 8;
    int qloc0 = (blockIdx.x & 255) * 8;

    const float* sev = g_s + (size_t)ev * Mq * SDQ;
    for (int i4 = tid; i4 < Mq * SDQ / 4; i4 += 256)
        ((float4*)ss)[i4] = ((const float4*)sev)[i4];
    __syncthreads();

    int qloc = qloc0 + w;
    int i = ev * Mq + qloc;
    float4 sq = ((float4*)ss)[qloc];

    // ---- distances (exactly the same FMA order as the passing version) ----
    unsigned bits[64];
    float fsum = 0.f;
    #pragma unroll
    for (int t = 0; t < 64; t++) {
        int j = lane + 32 * t;
        float4 sj = ((float4*)ss)[j];
        float dx = sq.x - sj.x, dy = sq.y - sj.y, dz = sq.z - sj.z, dw = sq.w - sj.w;
        float d2 = fmaf(dx, dx, fmaf(dy, dy, fmaf(dz, dz, dw * dw)));
        bits[t] = __float_as_uint(d2);
        fsum += d2;
    }
    #pragma unroll
    for (int o = 16; o; o >>= 1) fsum += __shfl_xor_sync(0xffffffffu, fsum, o);

    // ---- model-guided threshold search: want count in [Kq, CAND] ----
    float T  = fsum * (0.20f / 2048.f);     // count ~ c*T^2 in 4D
    float lo = 0.f, hi = 3.3e38f;
    unsigned Tsel = 0u;
    int c = 0;
    bool found = false;
    for (int it = 0; it < 16 && !found; ++it) {
        Tsel = __float_as_uint(T);
        c = 0;
        #pragma unroll
        for (int t = 0; t < 64; t++) c += (bits[t] <= Tsel) ? 1 : 0;
        c = __reduce_add_sync(0xffffffffu, c);
        if (c >= Kq && c <= CAND) { found = true; break; }
        if (c < Kq) {
            lo = T;
            float Tm = T * sqrtf(52.f / fmaxf((float)c, 2.f));
            if (hi < 3e38f) {
                float wdt = hi - lo;
                Tm = fminf(fmaxf(Tm, lo + 0.25f * wdt), lo + 0.75f * wdt);
            } else {
                Tm = fmaxf(Tm, T * 1.5f);
            }
            T = Tm;
        } else {
            hi = T;
            float Tm = T * sqrtf(80.f / (float)c);
            float wdt = hi - lo;
            Tm = fminf(fmaxf(Tm, lo + 0.25f * wdt), lo + 0.75f * wdt);
            T = Tm;
        }
    }
    if (!found) {   // exact bit-space bisection fallback (guaranteed)
        unsigned l = 0u, h = 0x7f800000u;
        for (int it = 0; it < 32 && !found; ++it) {
            unsigned mid = l + ((h - l) >> 1);
            int cc = 0;
            #pragma unroll
            for (int t = 0; t < 64; t++) cc += (bits[t] <= mid) ? 1 : 0;
            cc = __reduce_add_sync(0xffffffffu, cc);
            if (cc >= Kq && cc <= CAND) { Tsel = mid; c = cc; found = true; }
            else if (cc >= Kq) h = mid;
            else l = mid;
            if (!found && h - l <= 1u) {
                Tsel = h; found = true;
                int c2 = 0;
                #pragma unroll
                for (int t = 0; t < 64; t++) c2 += (bits[t] <= h) ? 1 : 0;
                c = __reduce_add_sync(0xffffffffu, c2);
            }
        }
    }

    // ---- compact candidates ----
    int base = 0;
    #pragma unroll
    for (int t = 0; t < 64; t++) {
        bool p = (bits[t] <= Tsel);
        unsigned m = __ballot_sync(0xffffffffu, p);
        if (p) {
            int pos = base + __popc(m & ((1u << lane) - 1u));
            if (pos < CAND)
                cand[w][pos] = ((unsigned long long)bits[t] << 32) | (unsigned)(lane + 32 * t);
        }
        base += __popc(m);
    }
    int C = base < CAND ? base : CAND;
    __syncwarp();

    // ---- load 4 keys/lane, pad, bitonic sort 128 ascending ----
    unsigned long long v[4];
    #pragma unroll
    for (int q = 0; q < 4; q++) {
        int e = q * 32 + lane;
        v[q] = (e < C) ? cand[w][e] : ~0ull;
    }
    #pragma unroll
    for (int kk = 2; kk <= 128; kk <<= 1) {
        #pragma unroll
        for (int j = kk >> 1; j > 0; j >>= 1) {
            if (j >= 32) {
                int qx = j >> 5;
                #pragma unroll
                for (int q = 0; q < 4; q++) {
                    if ((q & qx) == 0) {
                        int e = q * 32 + lane;
                        bool up = ((e & kk) == 0);
                        unsigned long long a = v[q], b = v[q | qx];
                        bool sw = up ? (a > b) : (a < b);
                        if (sw) { v[q] = b; v[q | qx] = a; }
                    }
                }
            } else {
                #pragma unroll
                for (int q = 0; q < 4; q++) {
                    int e = q * 32 + lane;
                    bool up = ((e & kk) == 0);
                    unsigned long long o = __shfl_xor_sync(0xffffffffu, v[q], j);
                    bool keepmin = (((lane & j) == 0) == up);
                    bool take = keepmin ? (o < v[q]) : (o > v[q]);
                    if (take) v[q] = o;
                }
            }
        }
    }

    // ---- top-40 broadcast: aggregation + edge output ----
    float meanAcc = 0.f;
    float maxAcc  = __int_as_float(0xff800000);
    const float* hev = g_h + (size_t)ev * Mq * PDQ;
    float* esrc = dout + ZOFF + (size_t)i * Kq;
    float* etgt = esrc + NKq;

    for (int r = 0; r < Kq; r++) {
        unsigned long long key = (r < 32) ? __shfl_sync(0xffffffffu, v[0], r)
                                          : __shfl_sync(0xffffffffu, v[1], r - 32);
        float d2  = __uint_as_float((unsigned)(key >> 32));
        int   j   = (int)(key & 0xffffffffu);
        float wgt = __expf(-10.f * d2);
        if (lane < PDQ) {
            float msg = hev[(size_t)j * PDQ + lane] * wgt;
            meanAcc += msg;
            maxAcc = fmaxf(maxAcc, msg);
        } else if (lane == 24) {
            esrc[r] = (float)(ev * Mq + j);
        } else if (lane == 25) {
            etgt[r] = (float)i;
        }
    }
    if (lane < PDQ) {
        float* ag = g_aggr + (size_t)i * 2 * PDQ;
        ag[lane]       = meanAcc * (1.f / (float)Kq);
        ag[PDQ + lane] = maxAcc;
    }
}

// ================= fast row-tiled SIMT GEMM (128 rows x OC per block) =====
// thread tile 8x8; A staged k-major in smem; all inner loads are LDS.128.
template<int KD, int OC, int KCH, int NT, bool DOTANH, bool EVBIAS>
__global__ __launch_bounds__(NT, 2) void gemm_k(
    const float* __restrict__ A, const float* __restrict__ W,
    const float* __restrict__ bias, float* __restrict__ Cf)
{
    constexpr int RT = 128, AST = 132, CG = OC / 8;
    extern __shared__ float sm[];
    float* As  = sm;                 // KCH * AST
    float* Wsm = sm + KCH * AST;     // KD * OC
    int tid = threadIdx.x;
    int rowBase = blockIdx.x * RT;

    for (int idx = tid; idx < KD * OC / 4; idx += NT)
        ((float4*)Wsm)[idx] = ((const float4*)W)[idx];

    int cg = tid % CG, rg = tid / CG;
    int r0 = rg * 8, c0 = cg * 8;

    float acc[8][8];
    {
        const float* bp = EVBIAS ? (bias + (rowBase >> 11) * 96) : bias;
        #pragma unroll
        for (int cc = 0; cc < 8; cc++) {
            float bv = bp[c0 + cc];
            #pragma unroll
            for (int r = 0; r < 8; r++) acc[r][cc] = bv;
        }
    }

    for (int kc = 0; kc < KD; kc += KCH) {
        __syncthreads();
        for (int idx = tid; idx < RT * KCH; idx += NT) {
            int r = idx / KCH, k = idx - r * KCH;
            As[k * AST + r] = A[(size_t)(rowBase + r) * KD + kc + k];
        }
        __syncthreads();
        #pragma unroll 8
        for (int k = 0; k < KCH; k++) {
            float4 a0 = *(const float4*)&As[k * AST + r0];
            float4 a1 = *(const float4*)&As[k * AST + r0 + 4];
            float4 w0 = *(const float4*)&Wsm[(kc + k) * OC + c0];
            float4 w1 = *(const float4*)&Wsm[(kc + k) * OC + c0 + 4];
            float av[8] = {a0.x, a0.y, a0.z, a0.w, a1.x, a1.y, a1.z, a1.w};
            float wv[8] = {w0.x, w0.y, w0.z, w0.w, w1.x, w1.y, w1.z, w1.w};
            #pragma unroll
            for (int r = 0; r < 8; r++)
                #pragma unroll
                for (int cc = 0; cc < 8; cc++)
                    acc[r][cc] = fmaf(av[r], wv[cc], acc[r][cc]);
        }
    }

    #pragma unroll
    for (int r = 0; r < 8; r++) {
        size_t rowoff = (size_t)(rowBase + r0 + r) * OC + c0;
        float4 o0, o1;
        if (DOTANH) {
            o0 = make_float4(fast_tanh(acc[r][0]), fast_tanh(acc[r][1]),
                             fast_tanh(acc[r][2]), fast_tanh(acc[r][3]));
            o1 = make_float4(fast_tanh(acc[r][4]), fast_tanh(acc[r][5]),
                             fast_tanh(acc[r][6]), fast_tanh(acc[r][7]));
        } else {
            o0 = make_float4(acc[r][0], acc[r][1], acc[r][2], acc[r][3]);
            o1 = make_float4(acc[r][4], acc[r][5], acc[r][6], acc[r][7]);
        }
        *(float4*)&Cf[rowoff]     = o0;
        *(float4*)&Cf[rowoff + 4] = o1;
    }
}

// ================= K2a: out = x@W_o1 + aggr@W_o2 + b_o2 ==================
__global__ __launch_bounds__(192, 2) void gemm_out_k(
    const float* __restrict__ x, const float* __restrict__ aggr,
    const float* __restrict__ Wo1, const float* __restrict__ Wo2,
    const float* __restrict__ bias, float* __restrict__ outp)
{
    constexpr int RT = 128, AST = 132, NT = 192, OC = 96;
    extern __shared__ float sm[];
    float* As  = sm;                     // 48*132
    float* Ws1 = sm + 48 * AST;          // 96*96
    float* Ws2 = Ws1 + 96 * 96;          // 44*96
    int tid = threadIdx.x;
    int rowBase = blockIdx.x * RT;

    for (int idx = tid; idx < 96 * 96 / 4; idx += NT)
        ((float4*)Ws1)[idx] = ((const float4*)Wo1)[idx];
    for (int idx = tid; idx < 44 * 96 / 4; idx += NT)
        ((float4*)Ws2)[idx] = ((const float4*)Wo2)[idx];

    int cg = tid % 12, rg = tid / 12;
    int r0 = rg * 8, c0 = cg * 8;

    float acc[8][8];
    #pragma unroll
    for (int cc = 0; cc < 8; cc++) {
        float bv = bias[c0 + cc];
        #pragma unroll
        for (int r = 0; r < 8; r++) acc[r][cc] = bv;
    }

    #pragma unroll
    for (int chunk = 0; chunk < 2; chunk++) {
        __syncthreads();
        for (int idx = tid; idx < RT * 48; idx += NT) {
            int r = idx / 48, k = idx - r * 48;
            As[k * AST + r] = x[(size_t)(rowBase + r) * 96 + chunk * 48 + k];
        }
        __syncthreads();
        #pragma unroll 8
        for (int k = 0; k < 48; k++) {
            float4 a0 = *(const float4*)&As[k * AST + r0];
            float4 a1 = *(const float4*)&As[k * AST + r0 + 4];
            float4 w0 = *(const float4*)&Ws1[(chunk * 48 + k) * OC + c0];
            float4 w1 = *(const float4*)&Ws1[(chunk * 48 + k) * OC + c0 + 4];
            float av[8] = {a0.x, a0.y, a0.z, a0.w, a1.x, a1.y, a1.z, a1.w};
            float wv[8] = {w0.x, w0.y, w0.z, w0.w, w1.x, w1.y, w1.z, w1.w};
            #pragma unroll
            for (int r = 0; r < 8; r++)
                #pragma unroll
                for (int cc = 0; cc < 8; cc++)
                    acc[r][cc] = fmaf(av[r], wv[cc], acc[r][cc]);
        }
    }
    // aggr chunk (KD2 = 44)
    __syncthreads();
    for (int idx = tid; idx < RT * 44; idx += NT) {
        int r = idx / 44, k = idx - r * 44;
        As[k * AST + r] = aggr[(size_t)(rowBase + r) * 44 + k];
    }
    __syncthreads();
    #pragma unroll 4
    for (int k = 0; k < 44; k++) {
        float4 a0 = *(const float4*)&As[k * AST + r0];
        float4 a1 = *(const float4*)&As[k * AST + r0 + 4];
        float4 w0 = *(const float4*)&Ws2[k * OC + c0];
        float4 w1 = *(const float4*)&Ws2[k * OC + c0 + 4];
        float av[8] = {a0.x, a0.y, a0.z, a0.w, a1.x, a1.y, a1.z, a1.w};
        float wv[8] = {w0.x, w0.y, w0.z, w0.w, w1.x, w1.y, w1.z, w1.w};
        #pragma unroll
        for (int r = 0; r < 8; r++)
            #pragma unroll
            for (int cc = 0; cc < 8; cc++)
                acc[r][cc] = fmaf(av[r], wv[cc], acc[r][cc]);
    }

    #pragma unroll
    for (int r = 0; r < 8; r++) {
        size_t rowoff = (size_t)(rowBase + r0 + r) * OC + c0;
        *(float4*)&outp[rowoff]     = make_float4(acc[r][0], acc[r][1], acc[r][2], acc[r][3]);
        *(float4*)&outp[rowoff + 4] = make_float4(acc[r][4], acc[r][5], acc[r][6], acc[r][7]);
    }
}

// ================= K3a: per-(event,chunk) partial mean/min/max ===========
__global__ __launch_bounds__(192) void stats1_k()
{
    int ev = blockIdx.x >> 4, ch = blockIdx.x & 15;
    int tid = threadIdx.x;
    int d = tid % 96, half = tid / 96;
    __shared__ float red[3][192];

    const float* yb = g_y + (size_t)ev * Mq * 96 + (size_t)ch * 128 * 96;
    float sm = 0.f, mn = __int_as_float(0x7f800000), mx = __int_as_float(0xff800000);
    for (int r = half; r < 128; r += 2) {
        float v = yb[(size_t)r * 96 + d];
        sm += v; mn = fminf(mn, v); mx = fmaxf(mx, v);
    }
    red[0][tid] = sm; red[1][tid] = mn; red[2][tid] = mx;
    __syncthreads();
    if (tid < 96) {
        float* p = g_part + ((size_t)(ev * 16 + ch) * 3) * 96;
        p[tid]        = red[0][tid] + red[0][tid + 96];
        p[96 + tid]   = fminf(red[1][tid], red[1][tid + 96]);
        p[192 + tid]  = fmaxf(red[2][tid], red[2][tid + 96]);
    }
}

// ================= K3b: reduce partials + stats@W3[0:288]+b3 =============
__global__ __launch_bounds__(96) void stats2_k(
    const float* __restrict__ W3, const float* __restrict__ b3)
{
    int ev = blockIdx.x, tid = threadIdx.x;
    __shared__ float st[288];

    float sm = 0.f, mn = __int_as_float(0x7f800000), mx = __int_as_float(0xff800000);
    for (int ch = 0; ch < 16; ch++) {
        const float* p = g_part + ((size_t)(ev * 16 + ch) * 3) * 96;
        sm += p[tid];
        mn = fminf(mn, p[96 + tid]);
        mx = fmaxf(mx, p[192 + tid]);
    }
    st[tid]       = sm * (1.f / (float)Mq);
    st[96 + tid]  = mn;
    st[192 + tid] = mx;
    __syncthreads();

    float acc = b3[tid];
    #pragma unroll 4
    for (int k = 0; k < 288; k++) acc = fmaf(st[k], W3[(size_t)k * 96 + tid], acc);
    g_c3[ev * 96 + tid] = acc;
}

// ================= host launcher =========================================
extern "C" void kernel_launch(void* const* d_in, const int* in_sizes, int n_in,
                              void* d_out, int out_size)
{
    (void)out_size;
    static const int EXPECTED[15] = {
        3145728, 32768, 384, 4, 2112, 22, 9216, 4224, 96, 12288, 128, 12288, 96, 36864, 96
    };
    const void* P[15];
    bool ok = (n_in >= 15);
    if (ok) for (int i = 0; i < 15; i++) if (in_sizes[i] != EXPECTED[i]) { ok = false; break; }
    if (ok) {
        for (int i = 0; i < 15; i++) P[i] = d_in[i];
    } else {
        bool used[64] = {false};
        for (int r = 0; r < 15; r++) {
            P[r] = nullptr;
            for (int j = 0; j < n_in && j < 64; j++) {
                if (!used[j] && in_sizes[j] == EXPECTED[r]) { P[r] = d_in[j]; used[j] = true; break; }
            }
        }
    }

    const float* x   = (const float*)P[0];
    const float* Ws  = (const float*)P[2];
    const float* bs  = (const float*)P[3];
    const float* Wh  = (const float*)P[4];
    const float* bh  = (const float*)P[5];
    const float* Wo1 = (const float*)P[6];
    const float* Wo2 = (const float*)P[7];
    const float* bo2 = (const float*)P[8];
    const float* W1  = (const float*)P[9];
    const float* b1  = (const float*)P[10];
    const float* W2  = (const float*)P[11];
    const float* b2  = (const float*)P[12];
    const float* W3  = (const float*)P[13];
    const float* b3  = (const float*)P[14];
    float* dout = (float*)d_out;

    float *p_aggr, *p_out, *p_t, *p_y, *p_c3;
    cudaGetSymbolAddress((void**)&p_aggr, g_aggr);
    cudaGetSymbolAddress((void**)&p_out,  g_out);
    cudaGetSymbolAddress((void**)&p_t,    g_t);
    cudaGetSymbolAddress((void**)&p_y,    g_y);
    cudaGetSymbolAddress((void**)&p_c3,   g_c3);

    const int SMEM_OUT = (48 * 132 + 96 * 96 + 44 * 96) * 4;   // 79104
    const int SMEM_B   = (96 * 132 + 96 * 128) * 4;            // 99840
    const int SMEM_C   = (64 * 132 + 128 * 96) * 4;            // 82944
    const int SMEM_Z   = (96 * 132 + 96 * 96) * 4;             // 87552
    cudaFuncSetAttribute(gemm_out_k, cudaFuncAttributeMaxDynamicSharedMemorySize, SMEM_OUT);
    cudaFuncSetAttribute(gemm_k<96, 128, 96, 256, true, false>,
                         cudaFuncAttributeMaxDynamicSharedMemorySize, SMEM_B);
    cudaFuncSetAttribute(gemm_k<128, 96, 64, 192, true, false>,
                         cudaFuncAttributeMaxDynamicSharedMemorySize, SMEM_C);
    cudaFuncSetAttribute(gemm_k<96, 96, 96, 192, true, true>,
                         cudaFuncAttributeMaxDynamicSharedMemorySize, SMEM_Z);

    sh_kernel<<<Nq / 8, 256>>>(x, Ws, bs, Wh, bh);
    knn_kernel<<<Nq / 8, 256>>>(dout);
    gemm_out_k<<<Nq / 128, 192, SMEM_OUT>>>(x, p_aggr, Wo1, Wo2, bo2, p_out);
    gemm_k<96, 128, 96, 256, true, false><<<Nq / 128, 256, SMEM_B>>>(p_out, W1, b1, p_t);
    gemm_k<128, 96, 64, 192, true, false><<<Nq / 128, 192, SMEM_C>>>(p_t, W2, b2, p_y);
    stats1_k<<<Bq * 16, 192>>>();
    stats2_k<<<Bq, 96>>>(W3, b3);
    gemm_k<96, 96, 96, 192, true, true><<<Nq / 128, 192, SMEM_Z>>>(p_y, W3 + 288 * 96, p_c3, dout);
}

// round 4
// speedup vs baseline: 1.1800x; 1.0168x over previous
#include <cuda_runtime.h>
#include <cstdint>

// ---------------- problem constants ----------------
#define Bq   16
#define Mq   2048
#define Kq   40
#define Nq   (Bq*Mq)      // 32768
#define INC  96
#define SDQ  4
#define PDQ  22
#define H1   128
#define CAND 128

static const size_t ZOFF = (size_t)Nq * 96;        // floats before edge_index
static const size_t NKq  = (size_t)Nq * Kq;

// ---------------- device scratch ----------------
__device__ float g_s[Nq * SDQ];
__device__ float g_h[Nq * PDQ];
__device__ float g_aggr[Nq * 2 * PDQ];
__device__ float g_out[Nq * 96];
__device__ float g_t[Nq * H1];
__device__ float g_y[Nq * 96];
__device__ float g_c3[Bq * 96];
__device__ float g_part[Bq * 16 * 3 * 96];

__device__ __forceinline__ float fast_tanh(float v) {
    float e = __expf(2.f * v);
    return (e - 1.f) * __frcp_rn(e + 1.f);
}

// ================= K0: s = x@W_s + b_s ; h = x@W_h + b_h =================
__global__ __launch_bounds__(256) void sh_kernel(
    const float* __restrict__ x,
    const float* __restrict__ Ws, const float* __restrict__ bs,
    const float* __restrict__ Wh, const float* __restrict__ bh)
{
    __shared__ float wsh[INC * 26];
    __shared__ float xs[8][INC];
    int tid = threadIdx.x;
    for (int idx = tid; idx < INC * 26; idx += 256) {
        int k = idx / 26, od = idx % 26;
        wsh[idx] = (od < SDQ) ? Ws[k * SDQ + od] : Wh[k * PDQ + (od - SDQ)];
    }
    const float* xb = x + (size_t)blockIdx.x * 8 * INC;
    for (int idx = tid; idx < 8 * INC; idx += 256) xs[idx / INC][idx % INC] = xb[idx];
    __syncthreads();

    int nl = tid >> 5, od = tid & 31;
    if (od < 26) {
        float acc = 0.f;
        #pragma unroll 8
        for (int k = 0; k < INC; k++) acc = fmaf(xs[nl][k], wsh[k * 26 + od], acc);
        int n = blockIdx.x * 8 + nl;
        if (od < SDQ) g_s[n * SDQ + od] = acc + bs[od];
        else          g_h[n * PDQ + (od - SDQ)] = acc + bh[od - SDQ];
    }
}

// ================= K1: kNN (smem-staged distances; low-register) ==========
// 1 warp per query, 8 warps/block. Distances written to per-warp smem array,
// re-read vectorized for threshold probes + compaction. Exact (d2bits,idx)
// keys -> bitonic sort 128 -> top-40 broadcast aggregation + edge output.
__global__ __launch_bounds__(256) void knn_kernel(float* __restrict__ dout)
{
    extern __shared__ float dsm[];
    float* ss  = dsm;                                  // 8192 f (32KB)
    float* d2s = dsm + Mq * SDQ;                       // 8*2048 f (64KB)
    unsigned long long* cand =
        (unsigned long long*)(dsm + Mq * SDQ + 8 * Mq); // 8*128 u64 (8KB)

    int tid  = threadIdx.x;
    int lane = tid & 31;
    int w    = tid >> 5;
    int ev    = blockIdx.x >> 8;
    int qloc0 = (blockIdx.x & 255) * 8;

    const float* sev = g_s + (size_t)ev * Mq * SDQ;
    for (int i4 = tid; i4 < Mq * SDQ / 4; i4 += 256)
        ((float4*)ss)[i4] = ((const float4*)sev)[i4];
    __syncthreads();

    int qloc = qloc0 + w;
    int i = ev * Mq + qloc;
    float4 sq = ((float4*)ss)[qloc];
    float* myd2 = d2s + w * Mq;

    // ---- distance pass: write to smem (element math identical to R3) ----
    float fsum = 0.f;
    #pragma unroll 8
    for (int t = 0; t < 64; t++) {
        int j = lane + 32 * t;
        float4 sj = ((float4*)ss)[j];
        float dx = sq.x - sj.x, dy = sq.y - sj.y, dz = sq.z - sj.z, dw = sq.w - sj.w;
        float d2 = fmaf(dx, dx, fmaf(dy, dy, fmaf(dz, dz, dw * dw)));
        myd2[j] = d2;
        fsum += d2;
    }
    #pragma unroll
    for (int o = 16; o; o >>= 1) fsum += __shfl_xor_sync(0xffffffffu, fsum, o);
    __syncwarp();

    const float4* dv = (const float4*)myd2;

    // ---- model-guided threshold search: want count in [Kq, CAND] ----
    float T  = fsum * (0.20f / 2048.f);
    float lo = 0.f, hi = 3.3e38f;
    unsigned Tsel = 0u;
    bool found = false;
    for (int it = 0; it < 16 && !found; ++it) {
        Tsel = __float_as_uint(T);
        int c = 0;
        #pragma unroll
        for (int t4 = 0; t4 < 16; t4++) {
            float4 vv = dv[lane + 32 * t4];
            c += (__float_as_uint(vv.x) <= Tsel) + (__float_as_uint(vv.y) <= Tsel)
               + (__float_as_uint(vv.z) <= Tsel) + (__float_as_uint(vv.w) <= Tsel);
        }
        c = __reduce_add_sync(0xffffffffu, c);
        if (c >= Kq && c <= CAND) { found = true; break; }
        if (c < Kq) {
            lo = T;
            float Tm = T * sqrtf(52.f / fmaxf((float)c, 2.f));
            if (hi < 3e38f) {
                float wdt = hi - lo;
                Tm = fminf(fmaxf(Tm, lo + 0.25f * wdt), lo + 0.75f * wdt);
            } else {
                Tm = fmaxf(Tm, T * 1.5f);
            }
            T = Tm;
        } else {
            hi = T;
            float Tm = T * sqrtf(80.f / (float)c);
            float wdt = hi - lo;
            Tm = fminf(fmaxf(Tm, lo + 0.25f * wdt), lo + 0.75f * wdt);
            T = Tm;
        }
    }
    if (!found) {   // exact bit-space bisection fallback (guaranteed)
        unsigned l = 0u, h = 0x7f800000u;
        for (int it = 0; it < 32 && !found; ++it) {
            unsigned mid = l + ((h - l) >> 1);
            int cc = 0;
            #pragma unroll
            for (int t4 = 0; t4 < 16; t4++) {
                float4 vv = dv[lane + 32 * t4];
                cc += (__float_as_uint(vv.x) <= mid) + (__float_as_uint(vv.y) <= mid)
                    + (__float_as_uint(vv.z) <= mid) + (__float_as_uint(vv.w) <= mid);
            }
            cc = __reduce_add_sync(0xffffffffu, cc);
            if (cc >= Kq && cc <= CAND) { Tsel = mid; found = true; }
            else if (cc >= Kq) h = mid;
            else l = mid;
            if (!found && h - l <= 1u) { Tsel = h; found = true; }
        }
    }

    // ---- compact candidates into per-warp smem buffer ----
    unsigned long long* mycand = cand + w * CAND;
    int base = 0;
    #pragma unroll
    for (int t4 = 0; t4 < 16; t4++) {
        float4 vv = dv[lane + 32 * t4];
        unsigned bb[4] = { __float_as_uint(vv.x), __float_as_uint(vv.y),
                           __float_as_uint(vv.z), __float_as_uint(vv.w) };
        int j0 = 4 * (lane + 32 * t4);
        #pragma unroll
        for (int e = 0; e < 4; e++) {
            bool p = (bb[e] <= Tsel);
            unsigned m = __ballot_sync(0xffffffffu, p);
            if (p) {
                int pos = base + __popc(m & ((1u << lane) - 1u));
                if (pos < CAND)
                    mycand[pos] = ((unsigned long long)bb[e] << 32) | (unsigned)(j0 + e);
            }
            base += __popc(m);
        }
    }
    int C = base < CAND ? base : CAND;
    __syncwarp();

    // ---- load 4 keys/lane, pad, bitonic sort 128 ascending ----
    unsigned long long v[4];
    #pragma unroll
    for (int q = 0; q < 4; q++) {
        int e = q * 32 + lane;
        v[q] = (e < C) ? mycand[e] : ~0ull;
    }
    #pragma unroll
    for (int kk = 2; kk <= 128; kk <<= 1) {
        #pragma unroll
        for (int j = kk >> 1; j > 0; j >>= 1) {
            if (j >= 32) {
                int qx = j >> 5;
                #pragma unroll
                for (int q = 0; q < 4; q++) {
                    if ((q & qx) == 0) {
                        int e = q * 32 + lane;
                        bool up = ((e & kk) == 0);
                        unsigned long long a = v[q], b = v[q | qx];
                        bool sw = up ? (a > b) : (a < b);
                        if (sw) { v[q] = b; v[q | qx] = a; }
                    }
                }
            } else {
                #pragma unroll
                for (int q = 0; q < 4; q++) {
                    int e = q * 32 + lane;
                    bool up = ((e & kk) == 0);
                    unsigned long long o = __shfl_xor_sync(0xffffffffu, v[q], j);
                    bool keepmin = (((lane & j) == 0) == up);
                    bool take = keepmin ? (o < v[q]) : (o > v[q]);
                    if (take) v[q] = o;
                }
            }
        }
    }

    // ---- top-40 broadcast: aggregation + edge output ----
    float meanAcc = 0.f;
    float maxAcc  = __int_as_float(0xff800000);
    const float* hev = g_h + (size_t)ev * Mq * PDQ;
    float* esrc = dout + ZOFF + (size_t)i * Kq;
    float* etgt = esrc + NKq;

    #pragma unroll 4
    for (int r = 0; r < Kq; r++) {
        unsigned long long key = (r < 32) ? __shfl_sync(0xffffffffu, v[0], r)
                                          : __shfl_sync(0xffffffffu, v[1], r - 32);
        float d2  = __uint_as_float((unsigned)(key >> 32));
        int   j   = (int)(key & 0xffffffffu);
        float wgt = __expf(-10.f * d2);
        if (lane < PDQ) {
            float msg = hev[(size_t)j * PDQ + lane] * wgt;
            meanAcc += msg;
            maxAcc = fmaxf(maxAcc, msg);
        } else if (lane == 24) {
            esrc[r] = (float)(ev * Mq + j);
        } else if (lane == 25) {
            etgt[r] = (float)i;
        }
    }
    if (lane < PDQ) {
        float* ag = g_aggr + (size_t)i * 2 * PDQ;
        ag[lane]       = meanAcc * (1.f / (float)Kq);
        ag[PDQ + lane] = maxAcc;
    }
}

// ================= fast row-tiled SIMT GEMM (128 rows x OC per block) =====
template<int KD, int OC, int KCH, int NT, bool DOTANH, bool EVBIAS>
__global__ __launch_bounds__(NT, 2) void gemm_k(
    const float* __restrict__ A, const float* __restrict__ W,
    const float* __restrict__ bias, float* __restrict__ Cf)
{
    constexpr int RT = 128, AST = 132, CG = OC / 8;
    extern __shared__ float sm[];
    float* As  = sm;
    float* Wsm = sm + KCH * AST;
    int tid = threadIdx.x;
    int rowBase = blockIdx.x * RT;

    for (int idx = tid; idx < KD * OC / 4; idx += NT)
        ((float4*)Wsm)[idx] = ((const float4*)W)[idx];

    int cg = tid % CG, rg = tid / CG;
    int r0 = rg * 8, c0 = cg * 8;

    float acc[8][8];
    {
        const float* bp = EVBIAS ? (bias + (rowBase >> 11) * 96) : bias;
        #pragma unroll
        for (int cc = 0; cc < 8; cc++) {
            float bv = bp[c0 + cc];
            #pragma unroll
            for (int r = 0; r < 8; r++) acc[r][cc] = bv;
        }
    }

    for (int kc = 0; kc < KD; kc += KCH) {
        __syncthreads();
        for (int idx = tid; idx < RT * KCH; idx += NT) {
            int r = idx / KCH, k = idx - r * KCH;
            As[k * AST + r] = A[(size_t)(rowBase + r) * KD + kc + k];
        }
        __syncthreads();
        #pragma unroll 8
        for (int k = 0; k < KCH; k++) {
            float4 a0 = *(const float4*)&As[k * AST + r0];
            float4 a1 = *(const float4*)&As[k * AST + r0 + 4];
            float4 w0 = *(const float4*)&Wsm[(kc + k) * OC + c0];
            float4 w1 = *(const float4*)&Wsm[(kc + k) * OC + c0 + 4];
            float av[8] = {a0.x, a0.y, a0.z, a0.w, a1.x, a1.y, a1.z, a1.w};
            float wv[8] = {w0.x, w0.y, w0.z, w0.w, w1.x, w1.y, w1.z, w1.w};
            #pragma unroll
            for (int r = 0; r < 8; r++)
                #pragma unroll
                for (int cc = 0; cc < 8; cc++)
                    acc[r][cc] = fmaf(av[r], wv[cc], acc[r][cc]);
        }
    }

    #pragma unroll
    for (int r = 0; r < 8; r++) {
        size_t rowoff = (size_t)(rowBase + r0 + r) * OC + c0;
        float4 o0, o1;
        if (DOTANH) {
            o0 = make_float4(fast_tanh(acc[r][0]), fast_tanh(acc[r][1]),
                             fast_tanh(acc[r][2]), fast_tanh(acc[r][3]));
            o1 = make_float4(fast_tanh(acc[r][4]), fast_tanh(acc[r][5]),
                             fast_tanh(acc[r][6]), fast_tanh(acc[r][7]));
        } else {
            o0 = make_float4(acc[r][0], acc[r][1], acc[r][2], acc[r][3]);
            o1 = make_float4(acc[r][4], acc[r][5], acc[r][6], acc[r][7]);
        }
        *(float4*)&Cf[rowoff]     = o0;
        *(float4*)&Cf[rowoff + 4] = o1;
    }
}

// ================= K2a: out = x@W_o1 + aggr@W_o2 + b_o2 ==================
__global__ __launch_bounds__(192, 2) void gemm_out_k(
    const float* __restrict__ x, const float* __restrict__ aggr,
    const float* __restrict__ Wo1, const float* __restrict__ Wo2,
    const float* __restrict__ bias, float* __restrict__ outp)
{
    constexpr int RT = 128, AST = 132, NT = 192, OC = 96;
    extern __shared__ float sm[];
    float* As  = sm;
    float* Ws1 = sm + 48 * AST;
    float* Ws2 = Ws1 + 96 * 96;
    int tid = threadIdx.x;
    int rowBase = blockIdx.x * RT;

    for (int idx = tid; idx < 96 * 96 / 4; idx += NT)
        ((float4*)Ws1)[idx] = ((const float4*)Wo1)[idx];
    for (int idx = tid; idx < 44 * 96 / 4; idx += NT)
        ((float4*)Ws2)[idx] = ((const float4*)Wo2)[idx];

    int cg = tid % 12, rg = tid / 12;
    int r0 = rg * 8, c0 = cg * 8;

    float acc[8][8];
    #pragma unroll
    for (int cc = 0; cc < 8; cc++) {
        float bv = bias[c0 + cc];
        #pragma unroll
        for (int r = 0; r < 8; r++) acc[r][cc] = bv;
    }

    #pragma unroll
    for (int chunk = 0; chunk < 2; chunk++) {
        __syncthreads();
        for (int idx = tid; idx < RT * 48; idx += NT) {
            int r = idx / 48, k = idx - r * 48;
            As[k * AST + r] = x[(size_t)(rowBase + r) * 96 + chunk * 48 + k];
        }
        __syncthreads();
        #pragma unroll 8
        for (int k = 0; k < 48; k++) {
            float4 a0 = *(const float4*)&As[k * AST + r0];
            float4 a1 = *(const float4*)&As[k * AST + r0 + 4];
            float4 w0 = *(const float4*)&Ws1[(chunk * 48 + k) * OC + c0];
            float4 w1 = *(const float4*)&Ws1[(chunk * 48 + k) * OC + c0 + 4];
            float av[8] = {a0.x, a0.y, a0.z, a0.w, a1.x, a1.y, a1.z, a1.w};
            float wv[8] = {w0.x, w0.y, w0.z, w0.w, w1.x, w1.y, w1.z, w1.w};
            #pragma unroll
            for (int r = 0; r < 8; r++)
                #pragma unroll
                for (int cc = 0; cc < 8; cc++)
                    acc[r][cc] = fmaf(av[r], wv[cc], acc[r][cc]);
        }
    }
    __syncthreads();
    for (int idx = tid; idx < RT * 44; idx += NT) {
        int r = idx / 44, k = idx - r * 44;
        As[k * AST + r] = aggr[(size_t)(rowBase + r) * 44 + k];
    }
    __syncthreads();
    #pragma unroll 4
    for (int k = 0; k < 44; k++) {
        float4 a0 = *(const float4*)&As[k * AST + r0];
        float4 a1 = *(const float4*)&As[k * AST + r0 + 4];
        float4 w0 = *(const float4*)&Ws2[k * OC + c0];
        float4 w1 = *(const float4*)&Ws2[k * OC + c0 + 4];
        float av[8] = {a0.x, a0.y, a0.z, a0.w, a1.x, a1.y, a1.z, a1.w};
        float wv[8] = {w0.x, w0.y, w0.z, w0.w, w1.x, w1.y, w1.z, w1.w};
        #pragma unroll
        for (int r = 0; r < 8; r++)
            #pragma unroll
            for (int cc = 0; cc < 8; cc++)
                acc[r][cc] = fmaf(av[r], wv[cc], acc[r][cc]);
    }

    #pragma unroll
    for (int r = 0; r < 8; r++) {
        size_t rowoff = (size_t)(rowBase + r0 + r) * OC + c0;
        *(float4*)&outp[rowoff]     = make_float4(acc[r][0], acc[r][1], acc[r][2], acc[r][3]);
        *(float4*)&outp[rowoff + 4] = make_float4(acc[r][4], acc[r][5], acc[r][6], acc[r][7]);
    }
}

// ================= K3a: per-(event,chunk) partial mean/min/max ===========
__global__ __launch_bounds__(192) void stats1_k()
{
    int ev = blockIdx.x >> 4, ch = blockIdx.x & 15;
    int tid = threadIdx.x;
    int d = tid % 96, half = tid / 96;
    __shared__ float red[3][192];

    const float* yb = g_y + (size_t)ev * Mq * 96 + (size_t)ch * 128 * 96;
    float sm = 0.f, mn = __int_as_float(0x7f800000), mx = __int_as_float(0xff800000);
    for (int r = half; r < 128; r += 2) {
        float v = yb[(size_t)r * 96 + d];
        sm += v; mn = fminf(mn, v); mx = fmaxf(mx, v);
    }
    red[0][tid] = sm; red[1][tid] = mn; red[2][tid] = mx;
    __syncthreads();
    if (tid < 96) {
        float* p = g_part + ((size_t)(ev * 16 + ch) * 3) * 96;
        p[tid]        = red[0][tid] + red[0][tid + 96];
        p[96 + tid]   = fminf(red[1][tid], red[1][tid + 96]);
        p[192 + tid]  = fmaxf(red[2][tid], red[2][tid + 96]);
    }
}

// ================= K3b: reduce partials + stats@W3[0:288]+b3 =============
__global__ __launch_bounds__(96) void stats2_k(
    const float* __restrict__ W3, const float* __restrict__ b3)
{
    int ev = blockIdx.x, tid = threadIdx.x;
    __shared__ float st[288];

    float sm = 0.f, mn = __int_as_float(0x7f800000), mx = __int_as_float(0xff800000);
    for (int ch = 0; ch < 16; ch++) {
        const float* p = g_part + ((size_t)(ev * 16 + ch) * 3) * 96;
        sm += p[tid];
        mn = fminf(mn, p[96 + tid]);
        mx = fmaxf(mx, p[192 + tid]);
    }
    st[tid]       = sm * (1.f / (float)Mq);
    st[96 + tid]  = mn;
    st[192 + tid] = mx;
    __syncthreads();

    float acc = b3[tid];
    #pragma unroll 4
    for (int k = 0; k < 288; k++) acc = fmaf(st[k], W3[(size_t)k * 96 + tid], acc);
    g_c3[ev * 96 + tid] = acc;
}

// ================= host launcher =========================================
extern "C" void kernel_launch(void* const* d_in, const int* in_sizes, int n_in,
                              void* d_out, int out_size)
{
    (void)out_size;
    static const int EXPECTED[15] = {
        3145728, 32768, 384, 4, 2112, 22, 9216, 4224, 96, 12288, 128, 12288, 96, 36864, 96
    };
    const void* P[15];
    bool ok = (n_in >= 15);
    if (ok) for (int i = 0; i < 15; i++) if (in_sizes[i] != EXPECTED[i]) { ok = false; break; }
    if (ok) {
        for (int i = 0; i < 15; i++) P[i] = d_in[i];
    } else {
        bool used[64] = {false};
        for (int r = 0; r < 15; r++) {
            P[r] = nullptr;
            for (int j = 0; j < n_in && j < 64; j++) {
                if (!used[j] && in_sizes[j] == EXPECTED[r]) { P[r] = d_in[j]; used[j] = true; break; }
            }
        }
    }

    const float* x   = (const float*)P[0];
    const float* Ws  = (const float*)P[2];
    const float* bs  = (const float*)P[3];
    const float* Wh  = (const float*)P[4];
    const float* bh  = (const float*)P[5];
    const float* Wo1 = (const float*)P[6];
    const float* Wo2 = (const float*)P[7];
    const float* bo2 = (const float*)P[8];
    const float* W1  = (const float*)P[9];
    const float* b1  = (const float*)P[10];
    const float* W2  = (const float*)P[11];
    const float* b2  = (const float*)P[12];
    const float* W3  = (const float*)P[13];
    const float* b3  = (const float*)P[14];
    float* dout = (float*)d_out;

    float *p_aggr, *p_out, *p_t, *p_y, *p_c3;
    cudaGetSymbolAddress((void**)&p_aggr, g_aggr);
    cudaGetSymbolAddress((void**)&p_out,  g_out);
    cudaGetSymbolAddress((void**)&p_t,    g_t);
    cudaGetSymbolAddress((void**)&p_y,    g_y);
    cudaGetSymbolAddress((void**)&p_c3,   g_c3);

    const int SMEM_KNN = (Mq * SDQ + 8 * Mq) * 4 + 8 * CAND * 8;  // 106496
    const int SMEM_OUT = (48 * 132 + 96 * 96 + 44 * 96) * 4;
    const int SMEM_B   = (96 * 132 + 96 * 128) * 4;
    const int SMEM_C   = (64 * 132 + 128 * 96) * 4;
    const int SMEM_Z   = (96 * 132 + 96 * 96) * 4;
    cudaFuncSetAttribute(knn_kernel, cudaFuncAttributeMaxDynamicSharedMemorySize, SMEM_KNN);
    cudaFuncSetAttribute(gemm_out_k, cudaFuncAttributeMaxDynamicSharedMemorySize, SMEM_OUT);
    cudaFuncSetAttribute(gemm_k<96, 128, 96, 256, true, false>,
                         cudaFuncAttributeMaxDynamicSharedMemorySize, SMEM_B);
    cudaFuncSetAttribute(gemm_k<128, 96, 64, 192, true, false>,
                         cudaFuncAttributeMaxDynamicSharedMemorySize, SMEM_C);
    cudaFuncSetAttribute(gemm_k<96, 96, 96, 192, true, true>,
                         cudaFuncAttributeMaxDynamicSharedMemorySize, SMEM_Z);

    sh_kernel<<<Nq / 8, 256>>>(x, Ws, bs, Wh, bh);
    knn_kernel<<<Nq / 8, 256, SMEM_KNN>>>(dout);
    gemm_out_k<<<Nq / 128, 192, SMEM_OUT>>>(x, p_aggr, Wo1, Wo2, bo2, p_out);
    gemm_k<96, 128, 96, 256, true, false><<<Nq / 128, 256, SMEM_B>>>(p_out, W1, b1, p_t);
    gemm_k<128, 96, 64, 192, true, false><<<Nq / 128, 192, SMEM_C>>>(p_t, W2, b2, p_y);
    stats1_k<<<Bq * 16, 192>>>();
    stats2_k<<<Bq, 96>>>(W3, b3);
    gemm_k<96, 96, 96, 192, true, true><<<Nq / 128, 192, SMEM_Z>>>(p_y, W3 + 288 * 96, p_c3, dout);
}

// round 6
// speedup vs baseline: 1.2251x; 1.0382x over previous
#include <cuda_runtime.h>
#include <cstdint>

// ---------------- problem constants ----------------
#define Bq   16
#define Mq   2048
#define Kq   40
#define Nq   (Bq*Mq)      // 32768
#define INC  96
#define SDQ  4
#define PDQ  22
#define H1   128
#define CAND 128

typedef unsigned long long ull;

static const size_t ZOFF = (size_t)Nq * 96;        // floats before edge_index
static const size_t NKq  = (size_t)Nq * Kq;

// ---------------- device scratch ----------------
__device__ float g_s[Nq * SDQ];
__device__ float g_h[Nq * PDQ];
__device__ float g_aggr[Nq * 2 * PDQ];
__device__ float g_out[Nq * 96];
__device__ float g_t[Nq * H1];
__device__ float g_y[Nq * 96];
__device__ float g_c3[Bq * 96];
__device__ float g_part[Bq * 16 * 3 * 96];

__device__ __forceinline__ float fast_tanh(float v) {
    float e = __expf(2.f * v);
    return (e - 1.f) * __frcp_rn(e + 1.f);
}

// ---------------- packed f32x2 helpers (sm_103a) ----------------
__device__ __forceinline__ ull pack2(float a, float b) {
    ull r; asm("mov.b64 %0, {%1,%2};" : "=l"(r) : "f"(a), "f"(b)); return r;
}
__device__ __forceinline__ float2 unpack2(ull v) {
    float2 f; asm("mov.b64 {%0,%1}, %2;" : "=f"(f.x), "=f"(f.y) : "l"(v)); return f;
}
__device__ __forceinline__ ull fma2(ull a, ull b, ull c) {
    ull d; asm("fma.rn.f32x2 %0, %1, %2, %3;" : "=l"(d) : "l"(a), "l"(b), "l"(c)); return d;
}

// ================= K0: s = x@W_s + b_s ; h = x@W_h + b_h =================
__global__ __launch_bounds__(256) void sh_kernel(
    const float* __restrict__ x,
    const float* __restrict__ Ws, const float* __restrict__ bs,
    const float* __restrict__ Wh, const float* __restrict__ bh)
{
    __shared__ float wsh[INC * 26];
    __shared__ float xs[32][INC];
    int tid = threadIdx.x;
    for (int idx = tid; idx < INC * 26; idx += 256) {
        int k = idx / 26, od = idx % 26;
        wsh[idx] = (od < SDQ) ? Ws[k * SDQ + od] : Wh[k * PDQ + (od - SDQ)];
    }
    const float* xb = x + (size_t)blockIdx.x * 32 * INC;
    for (int idx = tid; idx < 32 * INC / 4; idx += 256)
        ((float4*)xs)[idx] = ((const float4*)xb)[idx];
    __syncthreads();

    int w = tid >> 5, od = tid & 31;
    if (od < 26) {
        float bv = (od < SDQ) ? bs[od] : bh[od - SDQ];
        #pragma unroll
        for (int q = 0; q < 4; q++) {
            int nl = w * 4 + q;
            float acc = 0.f;
            #pragma unroll 8
            for (int k = 0; k < INC; k++) acc = fmaf(xs[nl][k], wsh[k * 26 + od], acc);
            int n = blockIdx.x * 32 + nl;
            if (od < SDQ) g_s[n * SDQ + od] = acc + bv;
            else          g_h[n * PDQ + (od - SDQ)] = acc + bv;
        }
    }
}

// ================= K1: kNN + weighted mean/max aggregation + edges =======
// 1 warp -> 4 queries sequential. SoA tile; scalar distances with the exact
// R4 fma ordering (bit-identical d2); warm-started threshold; exact u64 keys
// (d2bits<<32 | idx) bitonic sort 128; coalesced edge writes.
__global__ __launch_bounds__(256) void knn_kernel(float* __restrict__ dout)
{
    extern __shared__ float dsm[];
    float* sx = dsm;                  // 2048
    float* sy = dsm + 2048;
    float* sz = dsm + 4096;
    float* sw = dsm + 6144;
    float* d2s = dsm + 8192;          // 8 * 2048
    ull* cand = (ull*)(dsm + 8192 + 8 * 2048);  // 8 * 128 u64

    int tid  = threadIdx.x;
    int lane = tid & 31;
    int w    = tid >> 5;
    int ev     = blockIdx.x >> 6;                // 64 blocks / event
    int qbase0 = (blockIdx.x & 63) * 32;

    const float4* sev = (const float4*)(g_s + (size_t)ev * Mq * SDQ);
    for (int j = tid; j < Mq; j += 256) {
        float4 s = sev[j];
        sx[j] = s.x; sy[j] = s.y; sz[j] = s.z; sw[j] = s.w;
    }
    __syncthreads();

    float* myd2 = d2s + w * Mq;
    ull* mycand = cand + w * CAND;
    const float4* dv = (const float4*)myd2;
    const float* hev = g_h + (size_t)ev * Mq * PDQ;
    int evM = ev * Mq;
    float Twarm = -1.f;

    for (int q = 0; q < 4; q++) {
        int qloc = qbase0 + w * 4 + q;
        int i = evM + qloc;
        float sqx = sx[qloc], sqy = sy[qloc], sqz = sz[qloc], sqw = sw[qloc];

        // ---- distances: EXACT R4 fma chain; store to smem ----
        float fsum = 0.f;
        #pragma unroll 8
        for (int t = 0; t < 64; t++) {
            int j = lane + 32 * t;
            float dx = sqx - sx[j], dy = sqy - sy[j];
            float dz = sqz - sz[j], dw = sqw - sw[j];
            float d2 = fmaf(dx, dx, fmaf(dy, dy, fmaf(dz, dz, dw * dw)));
            myd2[j] = d2;
            fsum += d2;
        }
        #pragma unroll
        for (int o = 16; o; o >>= 1) fsum += __shfl_xor_sync(0xffffffffu, fsum, o);
        __syncwarp();

        // ---- threshold search: count in [Kq, CAND]; warm-start ----
        float T  = (Twarm > 0.f) ? Twarm : fsum * (0.20f / 2048.f);
        float lo = 0.f, hi = 3.3e38f;
        unsigned Tsel = 0u;
        bool found = false;
        for (int it = 0; it < 16 && !found; ++it) {
            Tsel = __float_as_uint(T);
            int c = 0;
            #pragma unroll
            for (int t4 = 0; t4 < 16; t4++) {
                float4 vv = dv[lane + 32 * t4];
                c += (__float_as_uint(vv.x) <= Tsel) + (__float_as_uint(vv.y) <= Tsel)
                   + (__float_as_uint(vv.z) <= Tsel) + (__float_as_uint(vv.w) <= Tsel);
            }
            c = __reduce_add_sync(0xffffffffu, c);
            if (c >= Kq && c <= CAND) { found = true; break; }
            if (c < Kq) {
                lo = T;
                float Tm = T * sqrtf(52.f / fmaxf((float)c, 2.f));
                if (hi < 3e38f) {
                    float wdt = hi - lo;
                    Tm = fminf(fmaxf(Tm, lo + 0.25f * wdt), lo + 0.75f * wdt);
                } else {
                    Tm = fmaxf(Tm, T * 1.5f);
                }
                T = Tm;
            } else {
                hi = T;
                float Tm = T * sqrtf(80.f / (float)c);
                float wdt = hi - lo;
                Tm = fminf(fmaxf(Tm, lo + 0.25f * wdt), lo + 0.75f * wdt);
                T = Tm;
            }
        }
        if (!found) {   // exact bit-space bisection fallback
            unsigned l = 0u, h = 0x7f800000u;
            for (int it = 0; it < 32 && !found; ++it) {
                unsigned mid = l + ((h - l) >> 1);
                int cc = 0;
                #pragma unroll
                for (int t4 = 0; t4 < 16; t4++) {
                    float4 vv = dv[lane + 32 * t4];
                    cc += (__float_as_uint(vv.x) <= mid) + (__float_as_uint(vv.y) <= mid)
                        + (__float_as_uint(vv.z) <= mid) + (__float_as_uint(vv.w) <= mid);
                }
                cc = __reduce_add_sync(0xffffffffu, cc);
                if (cc >= Kq && cc <= CAND) { Tsel = mid; found = true; }
                else if (cc >= Kq) h = mid;
                else l = mid;
                if (!found && h - l <= 1u) { Tsel = h; found = true; }
            }
        }
        Twarm = __uint_as_float(Tsel);

        // ---- compact candidates as EXACT u64 keys ----
        int base = 0;
        #pragma unroll
        for (int t4 = 0; t4 < 16; t4++) {
            float4 vv = dv[lane + 32 * t4];
            unsigned bb[4] = { __float_as_uint(vv.x), __float_as_uint(vv.y),
                               __float_as_uint(vv.z), __float_as_uint(vv.w) };
            int j0 = 4 * (lane + 32 * t4);
            #pragma unroll
            for (int e = 0; e < 4; e++) {
                bool p = (bb[e] <= Tsel);
                unsigned m = __ballot_sync(0xffffffffu, p);
                if (p) {
                    int pos = base + __popc(m & ((1u << lane) - 1u));
                    if (pos < CAND)
                        mycand[pos] = ((ull)bb[e] << 32) | (unsigned)(j0 + e);
                }
                base += __popc(m);
            }
        }
        int C = base < CAND ? base : CAND;
        __syncwarp();

        // ---- bitonic sort 128 u64 ascending (4 regs/lane) ----
        ull v[4];
        #pragma unroll
        for (int qq = 0; qq < 4; qq++) {
            int e = qq * 32 + lane;
            v[qq] = (e < C) ? mycand[e] : ~0ull;
        }
        #pragma unroll
        for (int kk = 2; kk <= 128; kk <<= 1) {
            #pragma unroll
            for (int j = kk >> 1; j > 0; j >>= 1) {
                if (j >= 32) {
                    int qx = j >> 5;
                    #pragma unroll
                    for (int qq = 0; qq < 4; qq++) {
                        if ((qq & qx) == 0) {
                            int e = qq * 32 + lane;
                            bool up = ((e & kk) == 0);
                            ull a = v[qq], b = v[qq | qx];
                            bool sw2 = up ? (a > b) : (a < b);
                            if (sw2) { v[qq] = b; v[qq | qx] = a; }
                        }
                    }
                } else {
                    #pragma unroll
                    for (int qq = 0; qq < 4; qq++) {
                        int e = qq * 32 + lane;
                        bool up = ((e & kk) == 0);
                        ull o = __shfl_xor_sync(0xffffffffu, v[qq], j);
                        bool keepmin = (((lane & j) == 0) == up);
                        bool take = keepmin ? (o < v[qq]) : (o > v[qq]);
                        if (take) v[qq] = o;
                    }
                }
            }
        }

        // ---- edge output: sorted rank == lane index -> coalesced ----
        float* esrc = dout + ZOFF + (size_t)i * Kq;
        float* etgt = esrc + NKq;
        esrc[lane] = (float)(evM + (int)(unsigned)(v[0] & 0xffffffffu));
        if (lane < 8)  esrc[32 + lane] = (float)(evM + (int)(unsigned)(v[1] & 0xffffffffu));
        if (lane < 10) *(float4*)&etgt[4 * lane] =
            make_float4((float)i, (float)i, (float)i, (float)i);

        // ---- top-40 broadcast aggregation (exact d2 from key) ----
        float meanAcc = 0.f;
        float maxAcc  = __int_as_float(0xff800000);
        #pragma unroll 4
        for (int r = 0; r < Kq; r++) {
            ull key = (r < 32) ? __shfl_sync(0xffffffffu, v[0], r)
                               : __shfl_sync(0xffffffffu, v[1], r - 32);
            float d2 = __uint_as_float((unsigned)(key >> 32));
            int j = (int)(unsigned)(key & 0xffffffffu);
            float wgt = __expf(-10.f * d2);
            if (lane < PDQ) {
                float msg = hev[(size_t)j * PDQ + lane] * wgt;
                meanAcc += msg;
                maxAcc = fmaxf(maxAcc, msg);
            }
        }
        if (lane < PDQ) {
            float* ag = g_aggr + (size_t)i * 2 * PDQ;
            ag[lane]       = meanAcc * (1.f / (float)Kq);
            ag[PDQ + lane] = maxAcc;
        }
        __syncwarp();
    }
}

// ================= row-tiled SIMT GEMM with packed f32x2 FMA ==============
template<int KD, int OC, int KCH, int NT, bool DOTANH, bool EVBIAS>
__global__ __launch_bounds__(NT, 2) void gemm_k(
    const float* __restrict__ A, const float* __restrict__ W,
    const float* __restrict__ bias, float* __restrict__ Cf)
{
    constexpr int RT = 128, AST = 132, CG = OC / 8;
    extern __shared__ float sm[];
    float* As  = sm;
    float* Wsm = sm + KCH * AST;
    int tid = threadIdx.x;
    int rowBase = blockIdx.x * RT;

    for (int idx = tid; idx < KD * OC / 4; idx += NT)
        ((float4*)Wsm)[idx] = ((const float4*)W)[idx];

    int cg = tid % CG, rg = tid / CG;
    int r0 = rg * 8, c0 = cg * 8;

    ull accp[4][8];
    {
        const float* bp = EVBIAS ? (bias + (rowBase >> 11) * 96) : bias;
        #pragma unroll
        for (int cc = 0; cc < 8; cc++) {
            ull bv = pack2(bp[c0 + cc], bp[c0 + cc]);
            #pragma unroll
            for (int rp = 0; rp < 4; rp++) accp[rp][cc] = bv;
        }
    }

    for (int kc = 0; kc < KD; kc += KCH) {
        __syncthreads();
        for (int idx = tid; idx < RT * KCH; idx += NT) {
            int r = idx / KCH, k = idx - r * KCH;
            As[k * AST + r] = A[(size_t)(rowBase + r) * KD + kc + k];
        }
        __syncthreads();
        #pragma unroll 8
        for (int k = 0; k < KCH; k++) {
            ulonglong2 a01 = *(const ulonglong2*)&As[k * AST + r0];
            ulonglong2 a23 = *(const ulonglong2*)&As[k * AST + r0 + 4];
            float4 w0 = *(const float4*)&Wsm[(kc + k) * OC + c0];
            float4 w1 = *(const float4*)&Wsm[(kc + k) * OC + c0 + 4];
            ull ap[4] = {a01.x, a01.y, a23.x, a23.y};
            ull wp[8] = {pack2(w0.x, w0.x), pack2(w0.y, w0.y),
                         pack2(w0.z, w0.z), pack2(w0.w, w0.w),
                         pack2(w1.x, w1.x), pack2(w1.y, w1.y),
                         pack2(w1.z, w1.z), pack2(w1.w, w1.w)};
            #pragma unroll
            for (int rp = 0; rp < 4; rp++)
                #pragma unroll
                for (int cc = 0; cc < 8; cc++)
                    accp[rp][cc] = fma2(ap[rp], wp[cc], accp[rp][cc]);
        }
    }

    #pragma unroll
    for (int rp = 0; rp < 4; rp++) {
        float vlo[8], vhi[8];
        #pragma unroll
        for (int cc = 0; cc < 8; cc++) {
            float2 f = unpack2(accp[rp][cc]);
            vlo[cc] = DOTANH ? fast_tanh(f.x) : f.x;
            vhi[cc] = DOTANH ? fast_tanh(f.y) : f.y;
        }
        size_t ro0 = (size_t)(rowBase + r0 + 2 * rp) * OC + c0;
        size_t ro1 = ro0 + OC;
        *(float4*)&Cf[ro0]     = make_float4(vlo[0], vlo[1], vlo[2], vlo[3]);
        *(float4*)&Cf[ro0 + 4] = make_float4(vlo[4], vlo[5], vlo[6], vlo[7]);
        *(float4*)&Cf[ro1]     = make_float4(vhi[0], vhi[1], vhi[2], vhi[3]);
        *(float4*)&Cf[ro1 + 4] = make_float4(vhi[4], vhi[5], vhi[6], vhi[7]);
    }
}

// ================= K2a: out = x@W_o1 + aggr@W_o2 + b_o2 (f32x2) ==========
__global__ __launch_bounds__(192, 2) void gemm_out_k(
    const float* __restrict__ x, const float* __restrict__ aggr,
    const float* __restrict__ Wo1, const float* __restrict__ Wo2,
    const float* __restrict__ bias, float* __restrict__ outp)
{
    constexpr int RT = 128, AST = 132, NT = 192, OC = 96;
    extern __shared__ float sm[];
    float* As  = sm;                     // 48*132
    float* Ws1 = sm + 48 * AST;          // 96*96
    float* Ws2 = Ws1 + 96 * 96;          // 44*96
    int tid = threadIdx.x;
    int rowBase = blockIdx.x * RT;

    for (int idx = tid; idx < 96 * 96 / 4; idx += NT)
        ((float4*)Ws1)[idx] = ((const float4*)Wo1)[idx];
    for (int idx = tid; idx < 44 * 96 / 4; idx += NT)
        ((float4*)Ws2)[idx] = ((const float4*)Wo2)[idx];

    int cg = tid % 12, rg = tid / 12;
    int r0 = rg * 8, c0 = cg * 8;

    ull accp[4][8];
    #pragma unroll
    for (int cc = 0; cc < 8; cc++) {
        ull bv = pack2(bias[c0 + cc], bias[c0 + cc]);
        #pragma unroll
        for (int rp = 0; rp < 4; rp++) accp[rp][cc] = bv;
    }

    #pragma unroll
    for (int chunk = 0; chunk < 2; chunk++) {
        __syncthreads();
        for (int idx = tid; idx < RT * 48; idx += NT) {
            int r = idx / 48, k = idx - r * 48;
            As[k * AST + r] = x[(size_t)(rowBase + r) * 96 + chunk * 48 + k];
        }
        __syncthreads();
        #pragma unroll 8
        for (int k = 0; k < 48; k++) {
            ulonglong2 a01 = *(const ulonglong2*)&As[k * AST + r0];
            ulonglong2 a23 = *(const ulonglong2*)&As[k * AST + r0 + 4];
            float4 w0 = *(const float4*)&Ws1[(chunk * 48 + k) * OC + c0];
            float4 w1 = *(const float4*)&Ws1[(chunk * 48 + k) * OC + c0 + 4];
            ull ap[4] = {a01.x, a01.y, a23.x, a23.y};
            ull wp[8] = {pack2(w0.x, w0.x), pack2(w0.y, w0.y),
                         pack2(w0.z, w0.z), pack2(w0.w, w0.w),
                         pack2(w1.x, w1.x), pack2(w1.y, w1.y),
                         pack2(w1.z, w1.z), pack2(w1.w, w1.w)};
            #pragma unroll
            for (int rp = 0; rp < 4; rp++)
                #pragma unroll
                for (int cc = 0; cc < 8; cc++)
                    accp[rp][cc] = fma2(ap[rp], wp[cc], accp[rp][cc]);
        }
    }
    __syncthreads();
    for (int idx = tid; idx < RT * 44; idx += NT) {
        int r = idx / 44, k = idx - r * 44;
        As[k * AST + r] = aggr[(size_t)(rowBase + r) * 44 + k];
    }
    __syncthreads();
    #pragma unroll 4
    for (int k = 0; k < 44; k++) {
        ulonglong2 a01 = *(const ulonglong2*)&As[k * AST + r0];
        ulonglong2 a23 = *(const ulonglong2*)&As[k * AST + r0 + 4];
        float4 w0 = *(const float4*)&Ws2[k * OC + c0];
        float4 w1 = *(const float4*)&Ws2[k * OC + c0 + 4];
        ull ap[4] = {a01.x, a01.y, a23.x, a23.y};
        ull wp[8] = {pack2(w0.x, w0.x), pack2(w0.y, w0.y),
                     pack2(w0.z, w0.z), pack2(w0.w, w0.w),
                     pack2(w1.x, w1.x), pack2(w1.y, w1.y),
                     pack2(w1.z, w1.z), pack2(w1.w, w1.w)};
        #pragma unroll
        for (int rp = 0; rp < 4; rp++)
            #pragma unroll
            for (int cc = 0; cc < 8; cc++)
                accp[rp][cc] = fma2(ap[rp], wp[cc], accp[rp][cc]);
    }

    #pragma unroll
    for (int rp = 0; rp < 4; rp++) {
        float vlo[8], vhi[8];
        #pragma unroll
        for (int cc = 0; cc < 8; cc++) {
            float2 f = unpack2(accp[rp][cc]);
            vlo[cc] = f.x; vhi[cc] = f.y;
        }
        size_t ro0 = (size_t)(rowBase + r0 + 2 * rp) * OC + c0;
        size_t ro1 = ro0 + OC;
        *(float4*)&outp[ro0]     = make_float4(vlo[0], vlo[1], vlo[2], vlo[3]);
        *(float4*)&outp[ro0 + 4] = make_float4(vlo[4], vlo[5], vlo[6], vlo[7]);
        *(float4*)&outp[ro1]     = make_float4(vhi[0], vhi[1], vhi[2], vhi[3]);
        *(float4*)&outp[ro1 + 4] = make_float4(vhi[4], vhi[5], vhi[6], vhi[7]);
    }
}

// ================= K3a: per-(event,chunk) partial mean/min/max ===========
__global__ __launch_bounds__(192) void stats1_k()
{
    int ev = blockIdx.x >> 4, ch = blockIdx.x & 15;
    int tid = threadIdx.x;
    int d = tid % 96, half = tid / 96;
    __shared__ float red[3][192];

    const float* yb = g_y + (size_t)ev * Mq * 96 + (size_t)ch * 128 * 96;
    float sm = 0.f, mn = __int_as_float(0x7f800000), mx = __int_as_float(0xff800000);
    for (int r = half; r < 128; r += 2) {
        float v = yb[(size_t)r * 96 + d];
        sm += v; mn = fminf(mn, v); mx = fmaxf(mx, v);
    }
    red[0][tid] = sm; red[1][tid] = mn; red[2][tid] = mx;
    __syncthreads();
    if (tid < 96) {
        float* p = g_part + ((size_t)(ev * 16 + ch) * 3) * 96;
        p[tid]        = red[0][tid] + red[0][tid + 96];
        p[96 + tid]   = fminf(red[1][tid], red[1][tid + 96]);
        p[192 + tid]  = fmaxf(red[2][tid], red[2][tid + 96]);
    }
}

// ================= K3b: reduce partials + stats@W3[0:288]+b3 =============
__global__ __launch_bounds__(96) void stats2_k(
    const float* __restrict__ W3, const float* __restrict__ b3)
{
    int ev = blockIdx.x, tid = threadIdx.x;
    __shared__ float st[288];

    float sm = 0.f, mn = __int_as_float(0x7f800000), mx = __int_as_float(0xff800000);
    for (int ch = 0; ch < 16; ch++) {
        const float* p = g_part + ((size_t)(ev * 16 + ch) * 3) * 96;
        sm += p[tid];
        mn = fminf(mn, p[96 + tid]);
        mx = fmaxf(mx, p[192 + tid]);
    }
    st[tid]       = sm * (1.f / (float)Mq);
    st[96 + tid]  = mn;
    st[192 + tid] = mx;
    __syncthreads();

    float acc = b3[tid];
    #pragma unroll 4
    for (int k = 0; k < 288; k++) acc = fmaf(st[k], W3[(size_t)k * 96 + tid], acc);
    g_c3[ev * 96 + tid] = acc;
}

// ================= host launcher =========================================
extern "C" void kernel_launch(void* const* d_in, const int* in_sizes, int n_in,
                              void* d_out, int out_size)
{
    (void)out_size;
    static const int EXPECTED[15] = {
        3145728, 32768, 384, 4, 2112, 22, 9216, 4224, 96, 12288, 128, 12288, 96, 36864, 96
    };
    const void* P[15];
    bool ok = (n_in >= 15);
    if (ok) for (int i = 0; i < 15; i++) if (in_sizes[i] != EXPECTED[i]) { ok = false; break; }
    if (ok) {
        for (int i = 0; i < 15; i++) P[i] = d_in[i];
    } else {
        bool used[64] = {false};
        for (int r = 0; r < 15; r++) {
            P[r] = nullptr;
            for (int j = 0; j < n_in && j < 64; j++) {
                if (!used[j] && in_sizes[j] == EXPECTED[r]) { P[r] = d_in[j]; used[j] = true; break; }
            }
        }
    }

    const float* x   = (const float*)P[0];
    const float* Ws  = (const float*)P[2];
    const float* bs  = (const float*)P[3];
    const float* Wh  = (const float*)P[4];
    const float* bh  = (const float*)P[5];
    const float* Wo1 = (const float*)P[6];
    const float* Wo2 = (const float*)P[7];
    const float* bo2 = (const float*)P[8];
    const float* W1  = (const float*)P[9];
    const float* b1  = (const float*)P[10];
    const float* W2  = (const float*)P[11];
    const float* b2  = (const float*)P[12];
    const float* W3  = (const float*)P[13];
    const float* b3  = (const float*)P[14];
    float* dout = (float*)d_out;

    float *p_aggr, *p_out, *p_t, *p_y, *p_c3;
    cudaGetSymbolAddress((void**)&p_aggr, g_aggr);
    cudaGetSymbolAddress((void**)&p_out,  g_out);
    cudaGetSymbolAddress((void**)&p_t,    g_t);
    cudaGetSymbolAddress((void**)&p_y,    g_y);
    cudaGetSymbolAddress((void**)&p_c3,   g_c3);

    const int SMEM_KNN = (8192 + 8 * 2048) * 4 + 8 * CAND * 8;  // 106496
    const int SMEM_OUT = (48 * 132 + 96 * 96 + 44 * 96) * 4;
    const int SMEM_B   = (96 * 132 + 96 * 128) * 4;
    const int SMEM_C   = (64 * 132 + 128 * 96) * 4;
    const int SMEM_Z   = (96 * 132 + 96 * 96) * 4;
    cudaFuncSetAttribute(knn_kernel, cudaFuncAttributeMaxDynamicSharedMemorySize, SMEM_KNN);
    cudaFuncSetAttribute(gemm_out_k, cudaFuncAttributeMaxDynamicSharedMemorySize, SMEM_OUT);
    cudaFuncSetAttribute(gemm_k<96, 128, 96, 256, true, false>,
                         cudaFuncAttributeMaxDynamicSharedMemorySize, SMEM_B);
    cudaFuncSetAttribute(gemm_k<128, 96, 64, 192, true, false>,
                         cudaFuncAttributeMaxDynamicSharedMemorySize, SMEM_C);
    cudaFuncSetAttribute(gemm_k<96, 96, 96, 192, true, true>,
                         cudaFuncAttributeMaxDynamicSharedMemorySize, SMEM_Z);

    sh_kernel<<<Nq / 32, 256>>>(x, Ws, bs, Wh, bh);
    knn_kernel<<<Nq / 32, 256, SMEM_KNN>>>(dout);
    gemm_out_k<<<Nq / 128, 192, SMEM_OUT>>>(x, p_aggr, Wo1, Wo2, bo2, p_out);
    gemm_k<96, 128, 96, 256, true, false><<<Nq / 128, 256, SMEM_B>>>(p_out, W1, b1, p_t);
    gemm_k<128, 96, 64, 192, true, false><<<Nq / 128, 192, SMEM_C>>>(p_t, W2, b2, p_y);
    stats1_k<<<Bq * 16, 192>>>();
    stats2_k<<<Bq, 96>>>(W3, b3);
    gemm_k<96, 96, 96, 192, true, true><<<Nq / 128, 192, SMEM_Z>>>(p_y, W3 + 288 * 96, p_c3, dout);
}

// round 7
// speedup vs baseline: 1.2426x; 1.0143x over previous
#include <cuda_runtime.h>
#include <cstdint>

// ---------------- problem constants ----------------
#define Bq   16
#define Mq   2048
#define Kq   40
#define Nq   (Bq*Mq)      // 32768
#define INC  96
#define SDQ  4
#define PDQ  22
#define H1   128
#define CAND 128

typedef unsigned long long ull;

static const size_t ZOFF = (size_t)Nq * 96;        // floats before edge_index
static const size_t NKq  = (size_t)Nq * Kq;

// ---------------- device scratch ----------------
__device__ float g_s[Nq * SDQ];
__device__ float g_h[Nq * PDQ];
__device__ float g_aggr[Nq * 2 * PDQ];
__device__ float g_out[Nq * 96];
__device__ float g_t[Nq * H1];
__device__ float g_y[Nq * 96];
__device__ float g_c3[Bq * 96];
__device__ float g_part[Bq * 16 * 3 * 96];

__device__ __forceinline__ float fast_tanh(float v) {
    float e = __expf(2.f * v);
    return (e - 1.f) * __frcp_rn(e + 1.f);
}

// ---------------- packed f32x2 helpers (sm_103a) ----------------
__device__ __forceinline__ ull pack2(float a, float b) {
    ull r; asm("mov.b64 %0, {%1,%2};" : "=l"(r) : "f"(a), "f"(b)); return r;
}
__device__ __forceinline__ float2 unpack2(ull v) {
    float2 f; asm("mov.b64 {%0,%1}, %2;" : "=f"(f.x), "=f"(f.y) : "l"(v)); return f;
}
__device__ __forceinline__ ull fma2(ull a, ull b, ull c) {
    ull d; asm("fma.rn.f32x2 %0, %1, %2, %3;" : "=l"(d) : "l"(a), "l"(b), "l"(c)); return d;
}

// exact distance: IDENTICAL fma chain to the passing R4/R6 kernels
__device__ __forceinline__ float d2exact(float sqx, float sqy, float sqz, float sqw,
                                         float jx, float jy, float jz, float jw) {
    float dx = sqx - jx, dy = sqy - jy, dz = sqz - jz, dw = sqw - jw;
    return fmaf(dx, dx, fmaf(dy, dy, fmaf(dz, dz, dw * dw)));
}

// ================= K0: s = x@W_s + b_s ; h = x@W_h + b_h =================
__global__ __launch_bounds__(256) void sh_kernel(
    const float* __restrict__ x,
    const float* __restrict__ Ws, const float* __restrict__ bs,
    const float* __restrict__ Wh, const float* __restrict__ bh)
{
    __shared__ float wsh[INC * 26];
    __shared__ float xs[32][INC];
    int tid = threadIdx.x;
    for (int idx = tid; idx < INC * 26; idx += 256) {
        int k = idx / 26, od = idx % 26;
        wsh[idx] = (od < SDQ) ? Ws[k * SDQ + od] : Wh[k * PDQ + (od - SDQ)];
    }
    const float* xb = x + (size_t)blockIdx.x * 32 * INC;
    for (int idx = tid; idx < 32 * INC / 4; idx += 256)
        ((float4*)xs)[idx] = ((const float4*)xb)[idx];
    __syncthreads();

    int w = tid >> 5, od = tid & 31;
    if (od < 26) {
        float bv = (od < SDQ) ? bs[od] : bh[od - SDQ];
        #pragma unroll
        for (int q = 0; q < 4; q++) {
            int nl = w * 4 + q;
            float acc = 0.f;
            #pragma unroll 8
            for (int k = 0; k < INC; k++) acc = fmaf(xs[nl][k], wsh[k * 26 + od], acc);
            int n = blockIdx.x * 32 + nl;
            if (od < SDQ) g_s[n * SDQ + od] = acc + bv;
            else          g_h[n * PDQ + (od - SDQ)] = acc + bv;
        }
    }
}

// ================= K1: kNN + weighted mean/max aggregation + edges =======
// 1 warp -> 4 queries. u16-truncated d2 staged in smem for SIMD threshold
// probes; exact d2 recomputed once (identical fma chain) for u64 keys.
// smem 72KB -> 3 CTAs/SM.
__global__ __launch_bounds__(256, 3) void knn_kernel(float* __restrict__ dout)
{
    extern __shared__ float dsm[];
    float* sx = dsm;                  // 2048
    float* sy = dsm + 2048;
    float* sz = dsm + 4096;
    float* sw = dsm + 6144;
    unsigned* d16 = (unsigned*)(dsm + 8192);          // 8 warps * 1024 u32 (32KB)
    ull* cand = (ull*)(dsm + 8192 + 8 * 1024);        // 8 * 128 u64 (8KB)

    int tid  = threadIdx.x;
    int lane = tid & 31;
    int w    = tid >> 5;
    int ev     = blockIdx.x >> 6;                // 64 blocks / event
    int qbase0 = (blockIdx.x & 63) * 32;

    const float4* sev = (const float4*)(g_s + (size_t)ev * Mq * SDQ);
    for (int j = tid; j < Mq; j += 256) {
        float4 s = sev[j];
        sx[j] = s.x; sy[j] = s.y; sz[j] = s.z; sw[j] = s.w;
    }
    __syncthreads();

    unsigned* myd16 = d16 + w * 1024;
    ull* mycand = cand + w * CAND;
    const uint4* dv16 = (const uint4*)myd16;
    const float* hev = g_h + (size_t)ev * Mq * PDQ;
    int evM = ev * Mq;
    float Twarm = -1.f;

    for (int q = 0; q < 4; q++) {
        int qloc = qbase0 + w * 4 + q;
        int i = evM + qloc;
        float sqx = sx[qloc], sqy = sy[qloc], sqz = sz[qloc], sqw = sw[qloc];

        // ---- distance pass: exact chain; stage truncated u16 pairs ----
        float fsum = 0.f;
        #pragma unroll 8
        for (int t = 0; t < 32; t++) {
            int p = lane + 32 * t;               // pair index; j = 2p, 2p+1
            float2 jx = *(const float2*)&sx[2 * p];
            float2 jy = *(const float2*)&sy[2 * p];
            float2 jz = *(const float2*)&sz[2 * p];
            float2 jw = *(const float2*)&sw[2 * p];
            float d2a = d2exact(sqx, sqy, sqz, sqw, jx.x, jy.x, jz.x, jw.x);
            float d2b = d2exact(sqx, sqy, sqz, sqw, jx.y, jy.y, jz.y, jw.y);
            myd16[p] = (__float_as_uint(d2a) >> 16) | (__float_as_uint(d2b) & 0xffff0000u);
            fsum += d2a + d2b;
        }
        #pragma unroll
        for (int o = 16; o; o >>= 1) fsum += __shfl_xor_sync(0xffffffffu, fsum, o);
        __syncwarp();

        // ---- threshold search in truncated u16 space; warm-start ----
        float T  = (Twarm > 0.f) ? Twarm : fsum * (0.20f / 2048.f);
        float lo = 0.f, hi = 3.3e38f;
        unsigned T16 = 0u;
        bool found = false;
        for (int it = 0; it < 16 && !found; ++it) {
            T16 = __float_as_uint(T) >> 16;
            unsigned TT = T16 * 0x10001u;
            unsigned acc = 0;
            #pragma unroll
            for (int t4 = 0; t4 < 8; t4++) {
                uint4 u = dv16[lane + 32 * t4];
                acc = __vadd2(acc, __vsetleu2(u.x, TT));
                acc = __vadd2(acc, __vsetleu2(u.y, TT));
                acc = __vadd2(acc, __vsetleu2(u.z, TT));
                acc = __vadd2(acc, __vsetleu2(u.w, TT));
            }
            int c = (int)((acc & 0xffffu) + (acc >> 16));
            c = __reduce_add_sync(0xffffffffu, c);
            if (c >= Kq && c <= CAND) { found = true; break; }
            if (c < Kq) {
                lo = T;
                float Tm = T * sqrtf(52.f / fmaxf((float)c, 2.f));
                if (hi < 3e38f) {
                    float wdt = hi - lo;
                    Tm = fminf(fmaxf(Tm, lo + 0.25f * wdt), lo + 0.75f * wdt);
                } else {
                    Tm = fmaxf(Tm, T * 1.5f);
                }
                T = Tm;
            } else {
                hi = T;
                float Tm = T * sqrtf(80.f / (float)c);
                float wdt = hi - lo;
                Tm = fminf(fmaxf(Tm, lo + 0.25f * wdt), lo + 0.75f * wdt);
                T = Tm;
            }
        }
        if (!found) {   // exact bisection in u16 space (guaranteed)
            unsigned l = 0u, h = 0x7f80u;
            for (int it = 0; it < 18 && !found; ++it) {
                unsigned mid = l + ((h - l) >> 1);
                unsigned TT = mid * 0x10001u;
                unsigned acc = 0;
                #pragma unroll
                for (int t4 = 0; t4 < 8; t4++) {
                    uint4 u = dv16[lane + 32 * t4];
                    acc = __vadd2(acc, __vsetleu2(u.x, TT));
                    acc = __vadd2(acc, __vsetleu2(u.y, TT));
                    acc = __vadd2(acc, __vsetleu2(u.z, TT));
                    acc = __vadd2(acc, __vsetleu2(u.w, TT));
                }
                int cc = (int)((acc & 0xffffu) + (acc >> 16));
                cc = __reduce_add_sync(0xffffffffu, cc);
                if (cc >= Kq && cc <= CAND) { T16 = mid; found = true; }
                else if (cc >= Kq) h = mid;
                else l = mid;
                if (!found && h - l <= 1u) { T16 = h; found = true; }
            }
        }
        Twarm = __uint_as_float((T16 << 16) | 0xffffu);

        // ---- compaction: recompute EXACT d2, keys (d2bits<<32 | j) ----
        int base = 0;
        #pragma unroll 4
        for (int t = 0; t < 64; t++) {
            int j = lane + 32 * t;
            float d2 = d2exact(sqx, sqy, sqz, sqw, sx[j], sy[j], sz[j], sw[j]);
            unsigned bb = __float_as_uint(d2);
            bool p = ((bb >> 16) <= T16);
            unsigned m = __ballot_sync(0xffffffffu, p);
            if (p) {
                int pos = base + __popc(m & ((1u << lane) - 1u));
                if (pos < CAND)
                    mycand[pos] = ((ull)bb << 32) | (unsigned)j;
            }
            base += __popc(m);
        }
        int C = base < CAND ? base : CAND;
        __syncwarp();

        // ---- bitonic sort 128 u64 ascending (4 regs/lane) ----
        ull v[4];
        #pragma unroll
        for (int qq = 0; qq < 4; qq++) {
            int e = qq * 32 + lane;
            v[qq] = (e < C) ? mycand[e] : ~0ull;
        }
        #pragma unroll
        for (int kk = 2; kk <= 128; kk <<= 1) {
            #pragma unroll
            for (int j = kk >> 1; j > 0; j >>= 1) {
                if (j >= 32) {
                    int qx = j >> 5;
                    #pragma unroll
                    for (int qq = 0; qq < 4; qq++) {
                        if ((qq & qx) == 0) {
                            int e = qq * 32 + lane;
                            bool up = ((e & kk) == 0);
                            ull a = v[qq], b = v[qq | qx];
                            bool sw2 = up ? (a > b) : (a < b);
                            if (sw2) { v[qq] = b; v[qq | qx] = a; }
                        }
                    }
                } else {
                    #pragma unroll
                    for (int qq = 0; qq < 4; qq++) {
                        int e = qq * 32 + lane;
                        bool up = ((e & kk) == 0);
                        ull o = __shfl_xor_sync(0xffffffffu, v[qq], j);
                        bool keepmin = (((lane & j) == 0) == up);
                        bool take = keepmin ? (o < v[qq]) : (o > v[qq]);
                        if (take) v[qq] = o;
                    }
                }
            }
        }

        // ---- edge output (coalesced) ----
        float* esrc = dout + ZOFF + (size_t)i * Kq;
        float* etgt = esrc + NKq;
        esrc[lane] = (float)(evM + (int)(unsigned)(v[0] & 0xffffffffu));
        if (lane < 8)  esrc[32 + lane] = (float)(evM + (int)(unsigned)(v[1] & 0xffffffffu));
        if (lane < 10) *(float4*)&etgt[4 * lane] =
            make_float4((float)i, (float)i, (float)i, (float)i);

        // ---- top-40 broadcast aggregation (exact d2 from key) ----
        float meanAcc = 0.f;
        float maxAcc  = __int_as_float(0xff800000);
        #pragma unroll 4
        for (int r = 0; r < Kq; r++) {
            ull key = (r < 32) ? __shfl_sync(0xffffffffu, v[0], r)
                               : __shfl_sync(0xffffffffu, v[1], r - 32);
            float d2 = __uint_as_float((unsigned)(key >> 32));
            int j = (int)(unsigned)(key & 0xffffffffu);
            float wgt = __expf(-10.f * d2);
            if (lane < PDQ) {
                float msg = hev[(size_t)j * PDQ + lane] * wgt;
                meanAcc += msg;
                maxAcc = fmaxf(maxAcc, msg);
            }
        }
        if (lane < PDQ) {
            float* ag = g_aggr + (size_t)i * 2 * PDQ;
            ag[lane]       = meanAcc * (1.f / (float)Kq);
            ag[PDQ + lane] = maxAcc;
        }
        __syncwarp();
    }
}

// ---- shared inner chunk: 8x8 thread tile, f32x2 FMA ----
template<int L, int OC>
__device__ __forceinline__ void mm_chunk(const float* __restrict__ As,
                                         const float* __restrict__ Wp,
                                         ull accp[4][8], int r0, int c0)
{
    constexpr int AST = 132;
    #pragma unroll 8
    for (int k = 0; k < L; k++) {
        ulonglong2 a01 = *(const ulonglong2*)&As[k * AST + r0];
        ulonglong2 a23 = *(const ulonglong2*)&As[k * AST + r0 + 4];
        float4 w0 = *(const float4*)&Wp[k * OC + c0];
        float4 w1 = *(const float4*)&Wp[k * OC + c0 + 4];
        ull ap[4] = {a01.x, a01.y, a23.x, a23.y};
        ull wp[8] = {pack2(w0.x, w0.x), pack2(w0.y, w0.y),
                     pack2(w0.z, w0.z), pack2(w0.w, w0.w),
                     pack2(w1.x, w1.x), pack2(w1.y, w1.y),
                     pack2(w1.z, w1.z), pack2(w1.w, w1.w)};
        #pragma unroll
        for (int rp = 0; rp < 4; rp++)
            #pragma unroll
            for (int cc = 0; cc < 8; cc++)
                accp[rp][cc] = fma2(ap[rp], wp[cc], accp[rp][cc]);
    }
}

template<int L, int NT>
__device__ __forceinline__ void stage_chunk(float* __restrict__ As,
                                            const float* __restrict__ src,
                                            int KD, int kc, int rowBase, int tid)
{
    constexpr int AST = 132;
    for (int idx = tid; idx < 128 * L; idx += NT) {
        int r = idx / L, k = idx - r * L;
        As[k * AST + r] = src[(size_t)(rowBase + r) * KD + kc + k];
    }
}

// ================= row-tiled GEMM, KCH=32, 3 CTAs/SM ======================
template<int KD, int OC, int NT, bool DOTANH, bool EVBIAS>
__global__ __launch_bounds__(NT, 3) void gemm_k(
    const float* __restrict__ A, const float* __restrict__ W,
    const float* __restrict__ bias, float* __restrict__ Cf)
{
    constexpr int RT = 128, AST = 132, CG = OC / 8, KCH = 32;
    extern __shared__ float sm[];
    float* As  = sm;                  // 32*132
    float* Wsm = sm + KCH * AST;      // KD*OC
    int tid = threadIdx.x;
    int rowBase = blockIdx.x * RT;

    for (int idx = tid; idx < KD * OC / 4; idx += NT)
        ((float4*)Wsm)[idx] = ((const float4*)W)[idx];

    int cg = tid % CG, rg = tid / CG;
    int r0 = rg * 8, c0 = cg * 8;

    ull accp[4][8];
    {
        const float* bp = EVBIAS ? (bias + (rowBase >> 11) * 96) : bias;
        #pragma unroll
        for (int cc = 0; cc < 8; cc++) {
            ull bv = pack2(bp[c0 + cc], bp[c0 + cc]);
            #pragma unroll
            for (int rp = 0; rp < 4; rp++) accp[rp][cc] = bv;
        }
    }

    #pragma unroll 1
    for (int kc = 0; kc < KD; kc += KCH) {
        __syncthreads();
        stage_chunk<KCH, NT>(As, A, KD, kc, rowBase, tid);
        __syncthreads();
        mm_chunk<KCH, OC>(As, Wsm + kc * OC, accp, r0, c0);
    }

    #pragma unroll
    for (int rp = 0; rp < 4; rp++) {
        float vlo[8], vhi[8];
        #pragma unroll
        for (int cc = 0; cc < 8; cc++) {
            float2 f = unpack2(accp[rp][cc]);
            vlo[cc] = DOTANH ? fast_tanh(f.x) : f.x;
            vhi[cc] = DOTANH ? fast_tanh(f.y) : f.y;
        }
        size_t ro0 = (size_t)(rowBase + r0 + 2 * rp) * OC + c0;
        size_t ro1 = ro0 + OC;
        *(float4*)&Cf[ro0]     = make_float4(vlo[0], vlo[1], vlo[2], vlo[3]);
        *(float4*)&Cf[ro0 + 4] = make_float4(vlo[4], vlo[5], vlo[6], vlo[7]);
        *(float4*)&Cf[ro1]     = make_float4(vhi[0], vhi[1], vhi[2], vhi[3]);
        *(float4*)&Cf[ro1 + 4] = make_float4(vhi[4], vhi[5], vhi[6], vhi[7]);
    }
}

// ================= K2a: out = x@W_o1 + aggr@W_o2 + b_o2 ==================
__global__ __launch_bounds__(192, 3) void gemm_out_k(
    const float* __restrict__ x, const float* __restrict__ aggr,
    const float* __restrict__ Wo1, const float* __restrict__ Wo2,
    const float* __restrict__ bias, float* __restrict__ outp)
{
    constexpr int RT = 128, AST = 132, NT = 192, OC = 96;
    extern __shared__ float sm[];
    float* As  = sm;                     // 32*132
    float* Ws1 = sm + 32 * AST;          // 96*96
    float* Ws2 = Ws1 + 96 * 96;          // 44*96
    int tid = threadIdx.x;
    int rowBase = blockIdx.x * RT;

    for (int idx = tid; idx < 96 * 96 / 4; idx += NT)
        ((float4*)Ws1)[idx] = ((const float4*)Wo1)[idx];
    for (int idx = tid; idx < 44 * 96 / 4; idx += NT)
        ((float4*)Ws2)[idx] = ((const float4*)Wo2)[idx];

    int cg = tid % 12, rg = tid / 12;
    int r0 = rg * 8, c0 = cg * 8;

    ull accp[4][8];
    #pragma unroll
    for (int cc = 0; cc < 8; cc++) {
        ull bv = pack2(bias[c0 + cc], bias[c0 + cc]);
        #pragma unroll
        for (int rp = 0; rp < 4; rp++) accp[rp][cc] = bv;
    }

    #pragma unroll 1
    for (int c = 0; c < 3; c++) {
        __syncthreads();
        stage_chunk<32, NT>(As, x, 96, c * 32, rowBase, tid);
        __syncthreads();
        mm_chunk<32, OC>(As, Ws1 + c * 32 * OC, accp, r0, c0);
    }
    __syncthreads();
    stage_chunk<32, NT>(As, aggr, 44, 0, rowBase, tid);
    __syncthreads();
    mm_chunk<32, OC>(As, Ws2, accp, r0, c0);
    __syncthreads();
    stage_chunk<12, NT>(As, aggr, 44, 32, rowBase, tid);
    __syncthreads();
    mm_chunk<12, OC>(As, Ws2 + 32 * OC, accp, r0, c0);

    #pragma unroll
    for (int rp = 0; rp < 4; rp++) {
        float vlo[8], vhi[8];
        #pragma unroll
        for (int cc = 0; cc < 8; cc++) {
            float2 f = unpack2(accp[rp][cc]);
            vlo[cc] = f.x; vhi[cc] = f.y;
        }
        size_t ro0 = (size_t)(rowBase + r0 + 2 * rp) * OC + c0;
        size_t ro1 = ro0 + OC;
        *(float4*)&outp[ro0]     = make_float4(vlo[0], vlo[1], vlo[2], vlo[3]);
        *(float4*)&outp[ro0 + 4] = make_float4(vlo[4], vlo[5], vlo[6], vlo[7]);
        *(float4*)&outp[ro1]     = make_float4(vhi[0], vhi[1], vhi[2], vhi[3]);
        *(float4*)&outp[ro1 + 4] = make_float4(vhi[4], vhi[5], vhi[6], vhi[7]);
    }
}

// ================= K3a: per-(event,chunk) partial mean/min/max ===========
__global__ __launch_bounds__(192) void stats1_k()
{
    int ev = blockIdx.x >> 4, ch = blockIdx.x & 15;
    int tid = threadIdx.x;
    int d = tid % 96, half = tid / 96;
    __shared__ float red[3][192];

    const float* yb = g_y + (size_t)ev * Mq * 96 + (size_t)ch * 128 * 96;
    float sm = 0.f, mn = __int_as_float(0x7f800000), mx = __int_as_float(0xff800000);
    for (int r = half; r < 128; r += 2) {
        float v = yb[(size_t)r * 96 + d];
        sm += v; mn = fminf(mn, v); mx = fmaxf(mx, v);
    }
    red[0][tid] = sm; red[1][tid] = mn; red[2][tid] = mx;
    __syncthreads();
    if (tid < 96) {
        float* p = g_part + ((size_t)(ev * 16 + ch) * 3) * 96;
        p[tid]        = red[0][tid] + red[0][tid + 96];
        p[96 + tid]   = fminf(red[1][tid], red[1][tid + 96]);
        p[192 + tid]  = fmaxf(red[2][tid], red[2][tid + 96]);
    }
}

// ================= K3b: reduce partials + stats@W3[0:288]+b3 =============
__global__ __launch_bounds__(96) void stats2_k(
    const float* __restrict__ W3, const float* __restrict__ b3)
{
    int ev = blockIdx.x, tid = threadIdx.x;
    __shared__ float st[288];

    float sm = 0.f, mn = __int_as_float(0x7f800000), mx = __int_as_float(0xff800000);
    for (int ch = 0; ch < 16; ch++) {
        const float* p = g_part + ((size_t)(ev * 16 + ch) * 3) * 96;
        sm += p[tid];
        mn = fminf(mn, p[96 + tid]);
        mx = fmaxf(mx, p[192 + tid]);
    }
    st[tid]       = sm * (1.f / (float)Mq);
    st[96 + tid]  = mn;
    st[192 + tid] = mx;
    __syncthreads();

    float acc = b3[tid];
    #pragma unroll 4
    for (int k = 0; k < 288; k++) acc = fmaf(st[k], W3[(size_t)k * 96 + tid], acc);
    g_c3[ev * 96 + tid] = acc;
}

// ================= host launcher =========================================
extern "C" void kernel_launch(void* const* d_in, const int* in_sizes, int n_in,
                              void* d_out, int out_size)
{
    (void)out_size;
    static const int EXPECTED[15] = {
        3145728, 32768, 384, 4, 2112, 22, 9216, 4224, 96, 12288, 128, 12288, 96, 36864, 96
    };
    const void* P[15];
    bool ok = (n_in >= 15);
    if (ok) for (int i = 0; i < 15; i++) if (in_sizes[i] != EXPECTED[i]) { ok = false; break; }
    if (ok) {
        for (int i = 0; i < 15; i++) P[i] = d_in[i];
    } else {
        bool used[64] = {false};
        for (int r = 0; r < 15; r++) {
            P[r] = nullptr;
            for (int j = 0; j < n_in && j < 64; j++) {
                if (!used[j] && in_sizes[j] == EXPECTED[r]) { P[r] = d_in[j]; used[j] = true; break; }
            }
        }
    }

    const float* x   = (const float*)P[0];
    const float* Ws  = (const float*)P[2];
    const float* bs  = (const float*)P[3];
    const float* Wh  = (const float*)P[4];
    const float* bh  = (const float*)P[5];
    const float* Wo1 = (const float*)P[6];
    const float* Wo2 = (const float*)P[7];
    const float* bo2 = (const float*)P[8];
    const float* W1  = (const float*)P[9];
    const float* b1  = (const float*)P[10];
    const float* W2  = (const float*)P[11];
    const float* b2  = (const float*)P[12];
    const float* W3  = (const float*)P[13];
    const float* b3  = (const float*)P[14];
    float* dout = (float*)d_out;

    float *p_aggr, *p_out, *p_t, *p_y, *p_c3;
    cudaGetSymbolAddress((void**)&p_aggr, g_aggr);
    cudaGetSymbolAddress((void**)&p_out,  g_out);
    cudaGetSymbolAddress((void**)&p_t,    g_t);
    cudaGetSymbolAddress((void**)&p_y,    g_y);
    cudaGetSymbolAddress((void**)&p_c3,   g_c3);

    const int SMEM_KNN = 8192 * 4 + 8 * 1024 * 4 + 8 * CAND * 8;   // 73728
    const int SMEM_OUT = (32 * 132 + 96 * 96 + 44 * 96) * 4;       // 70656
    const int SMEM_B   = (32 * 132 + 96 * 128) * 4;                // 66048
    const int SMEM_C   = (32 * 132 + 128 * 96) * 4;                // 66048
    const int SMEM_Z   = (32 * 132 + 96 * 96) * 4;                 // 53760
    cudaFuncSetAttribute(knn_kernel, cudaFuncAttributeMaxDynamicSharedMemorySize, SMEM_KNN);
    cudaFuncSetAttribute(gemm_out_k, cudaFuncAttributeMaxDynamicSharedMemorySize, SMEM_OUT);
    cudaFuncSetAttribute(gemm_k<96, 128, 256, true, false>,
                         cudaFuncAttributeMaxDynamicSharedMemorySize, SMEM_B);
    cudaFuncSetAttribute(gemm_k<128, 96, 192, true, false>,
                         cudaFuncAttributeMaxDynamicSharedMemorySize, SMEM_C);
    cudaFuncSetAttribute(gemm_k<96, 96, 192, true, true>,
                         cudaFuncAttributeMaxDynamicSharedMemorySize, SMEM_Z);

    sh_kernel<<<Nq / 32, 256>>>(x, Ws, bs, Wh, bh);
    knn_kernel<<<Nq / 32, 256, SMEM_KNN>>>(dout);
    gemm_out_k<<<Nq / 128, 192, SMEM_OUT>>>(x, p_aggr, Wo1, Wo2, bo2, p_out);
    gemm_k<96, 128, 256, true, false><<<Nq / 128, 256, SMEM_B>>>(p_out, W1, b1, p_t);
    gemm_k<128, 96, 192, true, false><<<Nq / 128, 192, SMEM_C>>>(p_t, W2, b2, p_y);
    stats1_k<<<Bq * 16, 192>>>();
    stats2_k<<<Bq, 96>>>(W3, b3);
    gemm_k<96, 96, 192, true, true><<<Nq / 128, 192, SMEM_Z>>>(p_y, W3 + 288 * 96, p_c3, dout);
}

// round 8
// speedup vs baseline: 1.4027x; 1.1288x over previous
#include <cuda_runtime.h>
#include <cstdint>

// ---------------- problem constants ----------------
#define Bq   16
#define Mq   2048
#define Kq   40
#define Nq   (Bq*Mq)      // 32768
#define INC  96
#define SDQ  4
#define PDQ  22
#define H1   128
#define CAND 128

typedef unsigned long long ull;

static const size_t ZOFF = (size_t)Nq * 96;        // floats before edge_index
static const size_t NKq  = (size_t)Nq * Kq;

// ---------------- device scratch ----------------
__device__ float g_s[Nq * SDQ];
__device__ float g_h[Nq * PDQ];
__device__ float g_aggr[Nq * 2 * PDQ];
__device__ float g_out[Nq * 96];
__device__ float g_t[Nq * H1];
__device__ float g_y[Nq * 96];
__device__ float g_c3[Bq * 96];
__device__ float g_part[Bq * 16 * 3 * 96];

__device__ __forceinline__ float fast_tanh(float v) {
    float e = __expf(2.f * v);
    return (e - 1.f) * __frcp_rn(e + 1.f);
}

// ---------------- packed f32x2 helpers (sm_103a) ----------------
__device__ __forceinline__ ull pack2(float a, float b) {
    ull r; asm("mov.b64 %0, {%1,%2};" : "=l"(r) : "f"(a), "f"(b)); return r;
}
__device__ __forceinline__ float2 unpack2(ull v) {
    float2 f; asm("mov.b64 {%0,%1}, %2;" : "=f"(f.x), "=f"(f.y) : "l"(v)); return f;
}
__device__ __forceinline__ ull fma2(ull a, ull b, ull c) {
    ull d; asm("fma.rn.f32x2 %0, %1, %2, %3;" : "=l"(d) : "l"(a), "l"(b), "l"(c)); return d;
}

// exact distance: IDENTICAL fma chain to the passing R4/R6/R7 kernels
__device__ __forceinline__ float d2exact(float sqx, float sqy, float sqz, float sqw,
                                         float jx, float jy, float jz, float jw) {
    float dx = sqx - jx, dy = sqy - jy, dz = sqz - jz, dw = sqw - jw;
    return fmaf(dx, dx, fmaf(dy, dy, fmaf(dz, dz, dw * dw)));
}

// ================= K0: s = x@W_s + b_s ; h = x@W_h + b_h =================
__global__ __launch_bounds__(256) void sh_kernel(
    const float* __restrict__ x,
    const float* __restrict__ Ws, const float* __restrict__ bs,
    const float* __restrict__ Wh, const float* __restrict__ bh)
{
    __shared__ float wsh[INC * 26];
    __shared__ float xs[32][INC];
    int tid = threadIdx.x;
    for (int idx = tid; idx < INC * 26; idx += 256) {
        int k = idx / 26, od = idx % 26;
        wsh[idx] = (od < SDQ) ? Ws[k * SDQ + od] : Wh[k * PDQ + (od - SDQ)];
    }
    const float* xb = x + (size_t)blockIdx.x * 32 * INC;
    for (int idx = tid; idx < 32 * INC / 4; idx += 256)
        ((float4*)xs)[idx] = ((const float4*)xb)[idx];
    __syncthreads();

    int w = tid >> 5, od = tid & 31;
    if (od < 26) {
        float bv = (od < SDQ) ? bs[od] : bh[od - SDQ];
        #pragma unroll
        for (int q = 0; q < 4; q++) {
            int nl = w * 4 + q;
            float acc = 0.f;
            #pragma unroll 8
            for (int k = 0; k < INC; k++) acc = fmaf(xs[nl][k], wsh[k * 26 + od], acc);
            int n = blockIdx.x * 32 + nl;
            if (od < SDQ) g_s[n * SDQ + od] = acc + bv;
            else          g_h[n * PDQ + (od - SDQ)] = acc + bv;
        }
    }
}

// ================= K1: kNN + weighted mean/max aggregation + edges =======
// (unchanged from R7 — u16 SIMD probes, exact recompute, 3 CTAs/SM)
__global__ __launch_bounds__(256, 3) void knn_kernel(float* __restrict__ dout)
{
    extern __shared__ float dsm[];
    float* sx = dsm;                  // 2048
    float* sy = dsm + 2048;
    float* sz = dsm + 4096;
    float* sw = dsm + 6144;
    unsigned* d16 = (unsigned*)(dsm + 8192);          // 8 warps * 1024 u32 (32KB)
    ull* cand = (ull*)(dsm + 8192 + 8 * 1024);        // 8 * 128 u64 (8KB)

    int tid  = threadIdx.x;
    int lane = tid & 31;
    int w    = tid >> 5;
    int ev     = blockIdx.x >> 6;                // 64 blocks / event
    int qbase0 = (blockIdx.x & 63) * 32;

    const float4* sev = (const float4*)(g_s + (size_t)ev * Mq * SDQ);
    for (int j = tid; j < Mq; j += 256) {
        float4 s = sev[j];
        sx[j] = s.x; sy[j] = s.y; sz[j] = s.z; sw[j] = s.w;
    }
    __syncthreads();

    unsigned* myd16 = d16 + w * 1024;
    ull* mycand = cand + w * CAND;
    const uint4* dv16 = (const uint4*)myd16;
    const float* hev = g_h + (size_t)ev * Mq * PDQ;
    int evM = ev * Mq;
    float Twarm = -1.f;

    for (int q = 0; q < 4; q++) {
        int qloc = qbase0 + w * 4 + q;
        int i = evM + qloc;
        float sqx = sx[qloc], sqy = sy[qloc], sqz = sz[qloc], sqw = sw[qloc];

        // ---- distance pass: exact chain; stage truncated u16 pairs ----
        float fsum = 0.f;
        #pragma unroll 8
        for (int t = 0; t < 32; t++) {
            int p = lane + 32 * t;               // pair index; j = 2p, 2p+1
            float2 jx = *(const float2*)&sx[2 * p];
            float2 jy = *(const float2*)&sy[2 * p];
            float2 jz = *(const float2*)&sz[2 * p];
            float2 jw = *(const float2*)&sw[2 * p];
            float d2a = d2exact(sqx, sqy, sqz, sqw, jx.x, jy.x, jz.x, jw.x);
            float d2b = d2exact(sqx, sqy, sqz, sqw, jx.y, jy.y, jz.y, jw.y);
            myd16[p] = (__float_as_uint(d2a) >> 16) | (__float_as_uint(d2b) & 0xffff0000u);
            fsum += d2a + d2b;
        }
        #pragma unroll
        for (int o = 16; o; o >>= 1) fsum += __shfl_xor_sync(0xffffffffu, fsum, o);
        __syncwarp();

        // ---- threshold search in truncated u16 space; warm-start ----
        float T  = (Twarm > 0.f) ? Twarm : fsum * (0.20f / 2048.f);
        float lo = 0.f, hi = 3.3e38f;
        unsigned T16 = 0u;
        bool found = false;
        for (int it = 0; it < 16 && !found; ++it) {
            T16 = __float_as_uint(T) >> 16;
            unsigned TT = T16 * 0x10001u;
            unsigned acc = 0;
            #pragma unroll
            for (int t4 = 0; t4 < 8; t4++) {
                uint4 u = dv16[lane + 32 * t4];
                acc = __vadd2(acc, __vsetleu2(u.x, TT));
                acc = __vadd2(acc, __vsetleu2(u.y, TT));
                acc = __vadd2(acc, __vsetleu2(u.z, TT));
                acc = __vadd2(acc, __vsetleu2(u.w, TT));
            }
            int c = (int)((acc & 0xffffu) + (acc >> 16));
            c = __reduce_add_sync(0xffffffffu, c);
            if (c >= Kq && c <= CAND) { found = true; break; }
            if (c < Kq) {
                lo = T;
                float Tm = T * sqrtf(52.f / fmaxf((float)c, 2.f));
                if (hi < 3e38f) {
                    float wdt = hi - lo;
                    Tm = fminf(fmaxf(Tm, lo + 0.25f * wdt), lo + 0.75f * wdt);
                } else {
                    Tm = fmaxf(Tm, T * 1.5f);
                }
                T = Tm;
            } else {
                hi = T;
                float Tm = T * sqrtf(80.f / (float)c);
                float wdt = hi - lo;
                Tm = fminf(fmaxf(Tm, lo + 0.25f * wdt), lo + 0.75f * wdt);
                T = Tm;
            }
        }
        if (!found) {   // exact bisection in u16 space (guaranteed)
            unsigned l = 0u, h = 0x7f80u;
            for (int it = 0; it < 18 && !found; ++it) {
                unsigned mid = l + ((h - l) >> 1);
                unsigned TT = mid * 0x10001u;
                unsigned acc = 0;
                #pragma unroll
                for (int t4 = 0; t4 < 8; t4++) {
                    uint4 u = dv16[lane + 32 * t4];
                    acc = __vadd2(acc, __vsetleu2(u.x, TT));
                    acc = __vadd2(acc, __vsetleu2(u.y, TT));
                    acc = __vadd2(acc, __vsetleu2(u.z, TT));
                    acc = __vadd2(acc, __vsetleu2(u.w, TT));
                }
                int cc = (int)((acc & 0xffffu) + (acc >> 16));
                cc = __reduce_add_sync(0xffffffffu, cc);
                if (cc >= Kq && cc <= CAND) { T16 = mid; found = true; }
                else if (cc >= Kq) h = mid;
                else l = mid;
                if (!found && h - l <= 1u) { T16 = h; found = true; }
            }
        }
        Twarm = __uint_as_float((T16 << 16) | 0xffffu);

        // ---- compaction: recompute EXACT d2, keys (d2bits<<32 | j) ----
        int base = 0;
        #pragma unroll 4
        for (int t = 0; t < 64; t++) {
            int j = lane + 32 * t;
            float d2 = d2exact(sqx, sqy, sqz, sqw, sx[j], sy[j], sz[j], sw[j]);
            unsigned bb = __float_as_uint(d2);
            bool p = ((bb >> 16) <= T16);
            unsigned m = __ballot_sync(0xffffffffu, p);
            if (p) {
                int pos = base + __popc(m & ((1u << lane) - 1u));
                if (pos < CAND)
                    mycand[pos] = ((ull)bb << 32) | (unsigned)j;
            }
            base += __popc(m);
        }
        int C = base < CAND ? base : CAND;
        __syncwarp();

        // ---- bitonic sort 128 u64 ascending (4 regs/lane) ----
        ull v[4];
        #pragma unroll
        for (int qq = 0; qq < 4; qq++) {
            int e = qq * 32 + lane;
            v[qq] = (e < C) ? mycand[e] : ~0ull;
        }
        #pragma unroll
        for (int kk = 2; kk <= 128; kk <<= 1) {
            #pragma unroll
            for (int j = kk >> 1; j > 0; j >>= 1) {
                if (j >= 32) {
                    int qx = j >> 5;
                    #pragma unroll
                    for (int qq = 0; qq < 4; qq++) {
                        if ((qq & qx) == 0) {
                            int e = qq * 32 + lane;
                            bool up = ((e & kk) == 0);
                            ull a = v[qq], b = v[qq | qx];
                            bool sw2 = up ? (a > b) : (a < b);
                            if (sw2) { v[qq] = b; v[qq | qx] = a; }
                        }
                    }
                } else {
                    #pragma unroll
                    for (int qq = 0; qq < 4; qq++) {
                        int e = qq * 32 + lane;
                        bool up = ((e & kk) == 0);
                        ull o = __shfl_xor_sync(0xffffffffu, v[qq], j);
                        bool keepmin = (((lane & j) == 0) == up);
                        bool take = keepmin ? (o < v[qq]) : (o > v[qq]);
                        if (take) v[qq] = o;
                    }
                }
            }
        }

        // ---- edge output (coalesced) ----
        float* esrc = dout + ZOFF + (size_t)i * Kq;
        float* etgt = esrc + NKq;
        esrc[lane] = (float)(evM + (int)(unsigned)(v[0] & 0xffffffffu));
        if (lane < 8)  esrc[32 + lane] = (float)(evM + (int)(unsigned)(v[1] & 0xffffffffu));
        if (lane < 10) *(float4*)&etgt[4 * lane] =
            make_float4((float)i, (float)i, (float)i, (float)i);

        // ---- top-40 broadcast aggregation (exact d2 from key) ----
        float meanAcc = 0.f;
        float maxAcc  = __int_as_float(0xff800000);
        #pragma unroll 4
        for (int r = 0; r < Kq; r++) {
            ull key = (r < 32) ? __shfl_sync(0xffffffffu, v[0], r)
                               : __shfl_sync(0xffffffffu, v[1], r - 32);
            float d2 = __uint_as_float((unsigned)(key >> 32));
            int j = (int)(unsigned)(key & 0xffffffffu);
            float wgt = __expf(-10.f * d2);
            if (lane < PDQ) {
                float msg = hev[(size_t)j * PDQ + lane] * wgt;
                meanAcc += msg;
                maxAcc = fmaxf(maxAcc, msg);
            }
        }
        if (lane < PDQ) {
            float* ag = g_aggr + (size_t)i * 2 * PDQ;
            ag[lane]       = meanAcc * (1.f / (float)Kq);
            ag[PDQ + lane] = maxAcc;
        }
        __syncwarp();
    }
}

// ================= row-tiled SIMT GEMM (R6 config: KCH big, 2 CTAs) =======
template<int KD, int OC, int KCH, int NT, bool DOTANH, bool EVBIAS>
__global__ __launch_bounds__(NT, 2) void gemm_k(
    const float* __restrict__ A, const float* __restrict__ W,
    const float* __restrict__ bias, float* __restrict__ Cf)
{
    constexpr int RT = 128, AST = 132, CG = OC / 8;
    extern __shared__ float sm[];
    float* As  = sm;
    float* Wsm = sm + KCH * AST;
    int tid = threadIdx.x;
    int rowBase = blockIdx.x * RT;

    for (int idx = tid; idx < KD * OC / 4; idx += NT)
        ((float4*)Wsm)[idx] = ((const float4*)W)[idx];

    int cg = tid % CG, rg = tid / CG;
    int r0 = rg * 8, c0 = cg * 8;

    ull accp[4][8];
    {
        const float* bp = EVBIAS ? (bias + (rowBase >> 11) * 96) : bias;
        #pragma unroll
        for (int cc = 0; cc < 8; cc++) {
            ull bv = pack2(bp[c0 + cc], bp[c0 + cc]);
            #pragma unroll
            for (int rp = 0; rp < 4; rp++) accp[rp][cc] = bv;
        }
    }

    for (int kc = 0; kc < KD; kc += KCH) {
        __syncthreads();
        for (int idx = tid; idx < RT * KCH; idx += NT) {
            int r = idx / KCH, k = idx - r * KCH;
            As[k * AST + r] = A[(size_t)(rowBase + r) * KD + kc + k];
        }
        __syncthreads();
        #pragma unroll 8
        for (int k = 0; k < KCH; k++) {
            ulonglong2 a01 = *(const ulonglong2*)&As[k * AST + r0];
            ulonglong2 a23 = *(const ulonglong2*)&As[k * AST + r0 + 4];
            float4 w0 = *(const float4*)&Wsm[(kc + k) * OC + c0];
            float4 w1 = *(const float4*)&Wsm[(kc + k) * OC + c0 + 4];
            ull ap[4] = {a01.x, a01.y, a23.x, a23.y};
            ull wp[8] = {pack2(w0.x, w0.x), pack2(w0.y, w0.y),
                         pack2(w0.z, w0.z), pack2(w0.w, w0.w),
                         pack2(w1.x, w1.x), pack2(w1.y, w1.y),
                         pack2(w1.z, w1.z), pack2(w1.w, w1.w)};
            #pragma unroll
            for (int rp = 0; rp < 4; rp++)
                #pragma unroll
                for (int cc = 0; cc < 8; cc++)
                    accp[rp][cc] = fma2(ap[rp], wp[cc], accp[rp][cc]);
        }
    }

    #pragma unroll
    for (int rp = 0; rp < 4; rp++) {
        float vlo[8], vhi[8];
        #pragma unroll
        for (int cc = 0; cc < 8; cc++) {
            float2 f = unpack2(accp[rp][cc]);
            vlo[cc] = DOTANH ? fast_tanh(f.x) : f.x;
            vhi[cc] = DOTANH ? fast_tanh(f.y) : f.y;
        }
        size_t ro0 = (size_t)(rowBase + r0 + 2 * rp) * OC + c0;
        size_t ro1 = ro0 + OC;
        *(float4*)&Cf[ro0]     = make_float4(vlo[0], vlo[1], vlo[2], vlo[3]);
        *(float4*)&Cf[ro0 + 4] = make_float4(vlo[4], vlo[5], vlo[6], vlo[7]);
        *(float4*)&Cf[ro1]     = make_float4(vhi[0], vhi[1], vhi[2], vhi[3]);
        *(float4*)&Cf[ro1 + 4] = make_float4(vhi[4], vhi[5], vhi[6], vhi[7]);
    }
}

// ================= K2a: out = x@W_o1 + aggr@W_o2 + b_o2 (R6 config) =======
__global__ __launch_bounds__(192, 2) void gemm_out_k(
    const float* __restrict__ x, const float* __restrict__ aggr,
    const float* __restrict__ Wo1, const float* __restrict__ Wo2,
    const float* __restrict__ bias, float* __restrict__ outp)
{
    constexpr int RT = 128, AST = 132, NT = 192, OC = 96;
    extern __shared__ float sm[];
    float* As  = sm;                     // 48*132
    float* Ws1 = sm + 48 * AST;          // 96*96
    float* Ws2 = Ws1 + 96 * 96;          // 44*96
    int tid = threadIdx.x;
    int rowBase = blockIdx.x * RT;

    for (int idx = tid; idx < 96 * 96 / 4; idx += NT)
        ((float4*)Ws1)[idx] = ((const float4*)Wo1)[idx];
    for (int idx = tid; idx < 44 * 96 / 4; idx += NT)
        ((float4*)Ws2)[idx] = ((const float4*)Wo2)[idx];

    int cg = tid % 12, rg = tid / 12;
    int r0 = rg * 8, c0 = cg * 8;

    ull accp[4][8];
    #pragma unroll
    for (int cc = 0; cc < 8; cc++) {
        ull bv = pack2(bias[c0 + cc], bias[c0 + cc]);
        #pragma unroll
        for (int rp = 0; rp < 4; rp++) accp[rp][cc] = bv;
    }

    #pragma unroll
    for (int chunk = 0; chunk < 2; chunk++) {
        __syncthreads();
        for (int idx = tid; idx < RT * 48; idx += NT) {
            int r = idx / 48, k = idx - r * 48;
            As[k * AST + r] = x[(size_t)(rowBase + r) * 96 + chunk * 48 + k];
        }
        __syncthreads();
        #pragma unroll 8
        for (int k = 0; k < 48; k++) {
            ulonglong2 a01 = *(const ulonglong2*)&As[k * AST + r0];
            ulonglong2 a23 = *(const ulonglong2*)&As[k * AST + r0 + 4];
            float4 w0 = *(const float4*)&Ws1[(chunk * 48 + k) * OC + c0];
            float4 w1 = *(const float4*)&Ws1[(chunk * 48 + k) * OC + c0 + 4];
            ull ap[4] = {a01.x, a01.y, a23.x, a23.y};
            ull wp[8] = {pack2(w0.x, w0.x), pack2(w0.y, w0.y),
                         pack2(w0.z, w0.z), pack2(w0.w, w0.w),
                         pack2(w1.x, w1.x), pack2(w1.y, w1.y),
                         pack2(w1.z, w1.z), pack2(w1.w, w1.w)};
            #pragma unroll
            for (int rp = 0; rp < 4; rp++)
                #pragma unroll
                for (int cc = 0; cc < 8; cc++)
                    accp[rp][cc] = fma2(ap[rp], wp[cc], accp[rp][cc]);
        }
    }
    __syncthreads();
    for (int idx = tid; idx < RT * 44; idx += NT) {
        int r = idx / 44, k = idx - r * 44;
        As[k * AST + r] = aggr[(size_t)(rowBase + r) * 44 + k];
    }
    __syncthreads();
    #pragma unroll 4
    for (int k = 0; k < 44; k++) {
        ulonglong2 a01 = *(const ulonglong2*)&As[k * AST + r0];
        ulonglong2 a23 = *(const ulonglong2*)&As[k * AST + r0 + 4];
        float4 w0 = *(const float4*)&Ws2[k * OC + c0];
        float4 w1 = *(const float4*)&Ws2[k * OC + c0 + 4];
        ull ap[4] = {a01.x, a01.y, a23.x, a23.y};
        ull wp[8] = {pack2(w0.x, w0.x), pack2(w0.y, w0.y),
                     pack2(w0.z, w0.z), pack2(w0.w, w0.w),
                     pack2(w1.x, w1.x), pack2(w1.y, w1.y),
                     pack2(w1.z, w1.z), pack2(w1.w, w1.w)};
        #pragma unroll
        for (int rp = 0; rp < 4; rp++)
            #pragma unroll
            for (int cc = 0; cc < 8; cc++)
                accp[rp][cc] = fma2(ap[rp], wp[cc], accp[rp][cc]);
    }

    #pragma unroll
    for (int rp = 0; rp < 4; rp++) {
        float vlo[8], vhi[8];
        #pragma unroll
        for (int cc = 0; cc < 8; cc++) {
            float2 f = unpack2(accp[rp][cc]);
            vlo[cc] = f.x; vhi[cc] = f.y;
        }
        size_t ro0 = (size_t)(rowBase + r0 + 2 * rp) * OC + c0;
        size_t ro1 = ro0 + OC;
        *(float4*)&outp[ro0]     = make_float4(vlo[0], vlo[1], vlo[2], vlo[3]);
        *(float4*)&outp[ro0 + 4] = make_float4(vlo[4], vlo[5], vlo[6], vlo[7]);
        *(float4*)&outp[ro1]     = make_float4(vhi[0], vhi[1], vhi[2], vhi[3]);
        *(float4*)&outp[ro1 + 4] = make_float4(vhi[4], vhi[5], vhi[6], vhi[7]);
    }
}

// ================= K3a: per-(event,chunk) partial mean/min/max ===========
__global__ __launch_bounds__(192) void stats1_k()
{
    int ev = blockIdx.x >> 4, ch = blockIdx.x & 15;
    int tid = threadIdx.x;
    int d = tid % 96, half = tid / 96;
    __shared__ float red[3][192];

    const float* yb = g_y + (size_t)ev * Mq * 96 + (size_t)ch * 128 * 96;
    float sm = 0.f, mn = __int_as_float(0x7f800000), mx = __int_as_float(0xff800000);
    for (int r = half; r < 128; r += 2) {
        float v = yb[(size_t)r * 96 + d];
        sm += v; mn = fminf(mn, v); mx = fmaxf(mx, v);
    }
    red[0][tid] = sm; red[1][tid] = mn; red[2][tid] = mx;
    __syncthreads();
    if (tid < 96) {
        float* p = g_part + ((size_t)(ev * 16 + ch) * 3) * 96;
        p[tid]        = red[0][tid] + red[0][tid + 96];
        p[96 + tid]   = fminf(red[1][tid], red[1][tid + 96]);
        p[192 + tid]  = fmaxf(red[2][tid], red[2][tid + 96]);
    }
}

// ================= K3b: reduce partials + stats@W3[0:288]+b3 =============
__global__ __launch_bounds__(96) void stats2_k(
    const float* __restrict__ W3, const float* __restrict__ b3)
{
    int ev = blockIdx.x, tid = threadIdx.x;
    __shared__ float st[288];

    float sm = 0.f, mn = __int_as_float(0x7f800000), mx = __int_as_float(0xff800000);
    for (int ch = 0; ch < 16; ch++) {
        const float* p = g_part + ((size_t)(ev * 16 + ch) * 3) * 96;
        sm += p[tid];
        mn = fminf(mn, p[96 + tid]);
        mx = fmaxf(mx, p[192 + tid]);
    }
    st[tid]       = sm * (1.f / (float)Mq);
    st[96 + tid]  = mn;
    st[192 + tid] = mx;
    __syncthreads();

    float acc = b3[tid];
    #pragma unroll 4
    for (int k = 0; k < 288; k++) acc = fmaf(st[k], W3[(size_t)k * 96 + tid], acc);
    g_c3[ev * 96 + tid] = acc;
}

// ================= host launcher =========================================
extern "C" void kernel_launch(void* const* d_in, const int* in_sizes, int n_in,
                              void* d_out, int out_size)
{
    (void)out_size;
    static const int EXPECTED[15] = {
        3145728, 32768, 384, 4, 2112, 22, 9216, 4224, 96, 12288, 128, 12288, 96, 36864, 96
    };
    const void* P[15];
    bool ok = (n_in >= 15);
    if (ok) for (int i = 0; i < 15; i++) if (in_sizes[i] != EXPECTED[i]) { ok = false; break; }
    if (ok) {
        for (int i = 0; i < 15; i++) P[i] = d_in[i];
    } else {
        bool used[64] = {false};
        for (int r = 0; r < 15; r++) {
            P[r] = nullptr;
            for (int j = 0; j < n_in && j < 64; j++) {
                if (!used[j] && in_sizes[j] == EXPECTED[r]) { P[r] = d_in[j]; used[j] = true; break; }
            }
        }
    }

    const float* x   = (const float*)P[0];
    const float* Ws  = (const float*)P[2];
    const float* bs  = (const float*)P[3];
    const float* Wh  = (const float*)P[4];
    const float* bh  = (const float*)P[5];
    const float* Wo1 = (const float*)P[6];
    const float* Wo2 = (const float*)P[7];
    const float* bo2 = (const float*)P[8];
    const float* W1  = (const float*)P[9];
    const float* b1  = (const float*)P[10];
    const float* W2  = (const float*)P[11];
    const float* b2  = (const float*)P[12];
    const float* W3  = (const float*)P[13];
    const float* b3  = (const float*)P[14];
    float* dout = (float*)d_out;

    float *p_aggr, *p_out, *p_t, *p_y, *p_c3;
    cudaGetSymbolAddress((void**)&p_aggr, g_aggr);
    cudaGetSymbolAddress((void**)&p_out,  g_out);
    cudaGetSymbolAddress((void**)&p_t,    g_t);
    cudaGetSymbolAddress((void**)&p_y,    g_y);
    cudaGetSymbolAddress((void**)&p_c3,   g_c3);

    const int SMEM_KNN = 8192 * 4 + 8 * 1024 * 4 + 8 * CAND * 8;   // 73728
    const int SMEM_OUT = (48 * 132 + 96 * 96 + 44 * 96) * 4;       // 79104
    const int SMEM_B   = (96 * 132 + 96 * 128) * 4;                // 99840
    const int SMEM_C   = (64 * 132 + 128 * 96) * 4;                // 82944
    const int SMEM_Z   = (96 * 132 + 96 * 96) * 4;                 // 87552
    cudaFuncSetAttribute(knn_kernel, cudaFuncAttributeMaxDynamicSharedMemorySize, SMEM_KNN);
    cudaFuncSetAttribute(gemm_out_k, cudaFuncAttributeMaxDynamicSharedMemorySize, SMEM_OUT);
    cudaFuncSetAttribute(gemm_k<96, 128, 96, 256, true, false>,
                         cudaFuncAttributeMaxDynamicSharedMemorySize, SMEM_B);
    cudaFuncSetAttribute(gemm_k<128, 96, 64, 192, true, false>,
                         cudaFuncAttributeMaxDynamicSharedMemorySize, SMEM_C);
    cudaFuncSetAttribute(gemm_k<96, 96, 96, 192, true, true>,
                         cudaFuncAttributeMaxDynamicSharedMemorySize, SMEM_Z);

    sh_kernel<<<Nq / 32, 256>>>(x, Ws, bs, Wh, bh);
    knn_kernel<<<Nq / 32, 256, SMEM_KNN>>>(dout);
    gemm_out_k<<<Nq / 128, 192, SMEM_OUT>>>(x, p_aggr, Wo1, Wo2, bo2, p_out);
    gemm_k<96, 128, 96, 256, true, false><<<Nq / 128, 256, SMEM_B>>>(p_out, W1, b1, p_t);
    gemm_k<128, 96, 64, 192, true, false><<<Nq / 128, 192, SMEM_C>>>(p_t, W2, b2, p_y);
    stats1_k<<<Bq * 16, 192>>>();
    stats2_k<<<Bq, 96>>>(W3, b3);
    gemm_k<96, 96, 96, 192, true, true><<<Nq / 128, 192, SMEM_Z>>>(p_y, W3 + 288 * 96, p_c3, dout);
}